// round 1
// baseline (speedup 1.0000x reference)
#include <cuda_runtime.h>
#include <cuda_bf16.h>
#include <cstdint>

#define B_   8
#define CIN  256
#define HW_  4096
#define DQK  16
#define NO_  288   // 16 + 16 + 256 packed output rows

// -------- scratch (device globals; no allocation allowed) --------
__device__ float d_fbuf[B_ * DQK * HW_];          // f [b][k][m]
__device__ float d_gbuf[B_ * DQK * HW_];          // g [b][k][n]
__device__ float d_hhT[(size_t)B_ * HW_ * CIN];   // hh transposed: [b][m][c]
__device__ float d_Wall[NO_ * CIN];
__device__ float d_ball[NO_];

// -------- pack weights --------
__global__ void prep_kernel(const float* __restrict__ Wf, const float* __restrict__ bf,
                            const float* __restrict__ Wg, const float* __restrict__ bg,
                            const float* __restrict__ Wh, const float* __restrict__ bh) {
    int i = blockIdx.x * blockDim.x + threadIdx.x;
    if (i < DQK * CIN) {
        d_Wall[i] = Wf[i];
        d_Wall[DQK * CIN + i] = Wg[i];
    }
    if (i < CIN * CIN) d_Wall[2 * DQK * CIN + i] = Wh[i];
    if (i < DQK) { d_ball[i] = bf[i]; d_ball[DQK + i] = bg[i]; }
    if (i < CIN) d_ball[2 * DQK + i] = bh[i];
}

// -------- projection GEMM: P[b,o,m] = sum_c Wall[o,c] * x[b,c,m] + ball[o] --------
// block tile: 32 o x 128 m, K looped in chunks of 32, 4x4 microtile per thread.
__global__ __launch_bounds__(256) void proj_kernel(const float* __restrict__ x) {
    const int b  = blockIdx.z;
    const int o0 = blockIdx.y * 32;
    const int m0 = blockIdx.x * 128;

    __shared__ float Ws[32][36];   // [k][o] (padded)
    __shared__ float Xs[32][128];  // [k][m]

    const int tid = threadIdx.x;
    const int tr = tid >> 5;   // 0..7 (o group of 4)
    const int tc = tid & 31;   // 0..31 (m group of 4)

    float acc[4][4];
#pragma unroll
    for (int i = 0; i < 4; i++) {
        float bia = d_ball[o0 + tr * 4 + i];
#pragma unroll
        for (int j = 0; j < 4; j++) acc[i][j] = bia;
    }

    const float* xb = x + (size_t)b * CIN * HW_;

    for (int kc = 0; kc < CIN; kc += 32) {
#pragma unroll
        for (int t = tid; t < 1024; t += 256) {
            int i = t >> 5, j = t & 31;             // i: o-local, j: k-local
            Ws[j][i] = d_Wall[(o0 + i) * CIN + kc + j];
        }
#pragma unroll
        for (int t = tid; t < 4096; t += 256) {
            int j = t >> 7, mm = t & 127;           // j: k-local
            Xs[j][mm] = xb[(size_t)(kc + j) * HW_ + m0 + mm];
        }
        __syncthreads();
#pragma unroll
        for (int kk = 0; kk < 32; kk++) {
            float4 wv = *(const float4*)&Ws[kk][tr * 4];
            float4 xv = *(const float4*)&Xs[kk][tc * 4];
            acc[0][0] += wv.x * xv.x; acc[0][1] += wv.x * xv.y; acc[0][2] += wv.x * xv.z; acc[0][3] += wv.x * xv.w;
            acc[1][0] += wv.y * xv.x; acc[1][1] += wv.y * xv.y; acc[1][2] += wv.y * xv.z; acc[1][3] += wv.y * xv.w;
            acc[2][0] += wv.z * xv.x; acc[2][1] += wv.z * xv.y; acc[2][2] += wv.z * xv.z; acc[2][3] += wv.z * xv.w;
            acc[3][0] += wv.w * xv.x; acc[3][1] += wv.w * xv.y; acc[3][2] += wv.w * xv.z; acc[3][3] += wv.w * xv.w;
        }
        __syncthreads();
    }

#pragma unroll
    for (int i = 0; i < 4; i++) {
        int o = o0 + tr * 4 + i;
#pragma unroll
        for (int j = 0; j < 4; j++) {
            int m = m0 + tc * 4 + j;
            float v = acc[i][j];
            if (o < DQK)            d_fbuf[((size_t)b * DQK + o) * HW_ + m] = v;
            else if (o < 2 * DQK)   d_gbuf[((size_t)b * DQK + (o - DQK)) * HW_ + m] = v;
            else                    d_hhT[((size_t)b * HW_ + m) * CIN + (o - 2 * DQK)] = v;
        }
    }
}

// -------- flash attention + residual --------
// grid: (HW/64, B); block: 256 threads. 4 threads per query row (cg = tid&3).
// smem: Ks[16][64] | Ps[64][65] | Vs[64][256]  = 86272 bytes
#define ATTN_SMEM_BYTES ((1024 + 64 * 65 + 64 * 256) * 4)

__global__ __launch_bounds__(256, 2) void attn_kernel(const float* __restrict__ x,
                                                      const float* __restrict__ gamma_p,
                                                      float* __restrict__ out) {
    extern __shared__ float sm[];
    float* Ks = sm;                    // 16*64
    float* Ps = sm + 1024;             // 64*65 (padded rows)
    float* Vs = sm + 1024 + 64 * 65;   // 64*256

    const int b  = blockIdx.y;
    const int n0 = blockIdx.x * 64;
    const int tid = threadIdx.x;
    const int q  = tid >> 2;   // 0..63
    const int cg = tid & 3;    // 0..3

    // query vector (16) into registers
    float qr[DQK];
    {
        const float* gq = d_gbuf + (size_t)b * DQK * HW_ + n0 + q;
#pragma unroll
        for (int k = 0; k < DQK; k++) qr[k] = gq[(size_t)k * HW_];
    }

    float4 acc[16];
#pragma unroll
    for (int j = 0; j < 16; j++) acc[j] = make_float4(0.f, 0.f, 0.f, 0.f);
    float row_max = -1e30f, row_sum = 0.f;

    const float* fb = d_fbuf + (size_t)b * DQK * HW_;
    const float* vb = d_hhT + (size_t)b * HW_ * CIN;

    for (int m0 = 0; m0 < HW_; m0 += 64) {
        __syncthreads();  // previous tile's Ps/Vs fully consumed
        // load K tile [16][64]
#pragma unroll
        for (int t = tid; t < 1024; t += 256)
            Ks[t] = fb[(size_t)(t >> 6) * HW_ + m0 + (t & 63)];
        // load V tile [64][256] (float4, coalesced)
        {
            const float4* vsrc = (const float4*)(vb + (size_t)m0 * CIN);
            float4* vdst = (float4*)Vs;
#pragma unroll
            for (int t = tid; t < 4096; t += 256) vdst[t] = vsrc[t];
        }
        __syncthreads();

        // ---- scoring: this thread handles m = cg*16 + i, i in [0,16) ----
        float s[16];
        float tmax = -1e30f;
#pragma unroll
        for (int i = 0; i < 16; i++) {
            int m = cg * 16 + i;
            float v = 0.f;
#pragma unroll
            for (int k = 0; k < DQK; k++) v += qr[k] * Ks[k * 64 + m];
            s[i] = v;
            tmax = fmaxf(tmax, v);
        }
        tmax = fmaxf(tmax, __shfl_xor_sync(0xffffffffu, tmax, 1));
        tmax = fmaxf(tmax, __shfl_xor_sync(0xffffffffu, tmax, 2));
        float nmax = fmaxf(row_max, tmax);
        float corr = __expf(row_max - nmax);
        float lsum = 0.f;
#pragma unroll
        for (int i = 0; i < 16; i++) {
            float p = __expf(s[i] - nmax);
            lsum += p;
            Ps[q * 65 + cg * 16 + i] = p;
        }
        lsum += __shfl_xor_sync(0xffffffffu, lsum, 1);
        lsum += __shfl_xor_sync(0xffffffffu, lsum, 2);
        row_sum = row_sum * corr + lsum;
        row_max = nmax;
#pragma unroll
        for (int j = 0; j < 16; j++) {
            acc[j].x *= corr; acc[j].y *= corr; acc[j].z *= corr; acc[j].w *= corr;
        }
        __syncthreads();  // Ps visible

        // ---- accumulate: acc[c] += P[q][m] * V[m][c]; channels interleaved by cg ----
#pragma unroll 2
        for (int i = 0; i < 64; i++) {
            float p = Ps[q * 65 + i];
            const float4* v4 = (const float4*)(Vs + i * 256);
#pragma unroll
            for (int j = 0; j < 16; j++) {
                float4 v = v4[cg + 4 * j];
                acc[j].x += p * v.x; acc[j].y += p * v.y;
                acc[j].z += p * v.z; acc[j].w += p * v.w;
            }
        }
    }

    // ---- epilogue: out = gamma * (acc / row_sum) + x ----
    const float inv = 1.f / row_sum;
    const float gm = *gamma_p;
    const float* xb = x + (size_t)b * CIN * HW_;
    float* ob = out + (size_t)b * CIN * HW_;
    const int n = n0 + q;
#pragma unroll
    for (int j = 0; j < 16; j++) {
        int cbase = 4 * (cg + 4 * j);
        float4 a = acc[j];
        ob[(size_t)(cbase + 0) * HW_ + n] = gm * a.x * inv + xb[(size_t)(cbase + 0) * HW_ + n];
        ob[(size_t)(cbase + 1) * HW_ + n] = gm * a.y * inv + xb[(size_t)(cbase + 1) * HW_ + n];
        ob[(size_t)(cbase + 2) * HW_ + n] = gm * a.z * inv + xb[(size_t)(cbase + 2) * HW_ + n];
        ob[(size_t)(cbase + 3) * HW_ + n] = gm * a.w * inv + xb[(size_t)(cbase + 3) * HW_ + n];
    }
}

extern "C" void kernel_launch(void* const* d_in, const int* in_sizes, int n_in,
                              void* d_out, int out_size) {
    const float* x  = (const float*)d_in[0];
    const float* Wf = (const float*)d_in[1];
    const float* bf = (const float*)d_in[2];
    const float* Wg = (const float*)d_in[3];
    const float* bg = (const float*)d_in[4];
    const float* Wh = (const float*)d_in[5];
    const float* bh = (const float*)d_in[6];
    const float* gamma = (const float*)d_in[7];
    float* out = (float*)d_out;

    prep_kernel<<<(CIN * CIN + 255) / 256, 256>>>(Wf, bf, Wg, bg, Wh, bh);
    proj_kernel<<<dim3(HW_ / 128, NO_ / 32, B_), 256>>>(x);

    cudaFuncSetAttribute(attn_kernel, cudaFuncAttributeMaxDynamicSharedMemorySize,
                         ATTN_SMEM_BYTES);
    attn_kernel<<<dim3(HW_ / 64, B_), 256, ATTN_SMEM_BYTES>>>(x, gamma, out);
}

// round 2
// speedup vs baseline: 1.7231x; 1.7231x over previous
#include <cuda_runtime.h>
#include <cuda_bf16.h>
#include <cstdint>

#define B_   8
#define CIN  256
#define HW_  4096
#define DQK  16
#define NO_  288   // 16 + 16 + 256 packed output rows

typedef unsigned long long u64;

// packed f32x2 ops (sm_103a FFMA2 — only reachable via PTX)
#define FMA2(d, a, b, c) asm("fma.rn.f32x2 %0, %1, %2, %3;" : "=l"(d) : "l"(a), "l"(b), "l"(c))
#define MUL2(d, a, b)    asm("mul.rn.f32x2 %0, %1, %2;"     : "=l"(d) : "l"(a), "l"(b))
#define PACK2(d, lo, hi) asm("mov.b64 %0, {%1, %2};"        : "=l"(d) : "r"(lo), "r"(hi))
#define UNPACK2(lo, hi, s) asm("mov.b64 {%0, %1}, %2;"      : "=r"(lo), "=r"(hi) : "l"(s))

// -------- scratch (device globals; no allocation allowed) --------
__device__ float d_fbuf[B_ * DQK * HW_];          // f [b][k][m]
__device__ float d_gbuf[B_ * DQK * HW_];          // g [b][k][n]
__device__ float d_hhT[(size_t)B_ * HW_ * CIN];   // hh transposed: [b][m][c]
__device__ float d_Wall[NO_ * CIN];
__device__ float d_ball[NO_];

// -------- pack weights --------
__global__ void prep_kernel(const float* __restrict__ Wf, const float* __restrict__ bf,
                            const float* __restrict__ Wg, const float* __restrict__ bg,
                            const float* __restrict__ Wh, const float* __restrict__ bh) {
    int i = blockIdx.x * blockDim.x + threadIdx.x;
    if (i < DQK * CIN) {
        d_Wall[i] = Wf[i];
        d_Wall[DQK * CIN + i] = Wg[i];
    }
    if (i < CIN * CIN) d_Wall[2 * DQK * CIN + i] = Wh[i];
    if (i < DQK) { d_ball[i] = bf[i]; d_ball[DQK + i] = bg[i]; }
    if (i < CIN) d_ball[2 * DQK + i] = bh[i];
}

// -------- projection GEMM: P[b,o,m] = sum_c Wall[o,c] * x[b,c,m] + ball[o] --------
__global__ __launch_bounds__(256) void proj_kernel(const float* __restrict__ x) {
    const int b  = blockIdx.z;
    const int o0 = blockIdx.y * 32;
    const int m0 = blockIdx.x * 128;

    __shared__ float Ws[32][36];   // [k][o] (padded)
    __shared__ float Xs[32][128];  // [k][m]

    const int tid = threadIdx.x;
    const int tr = tid >> 5;   // 0..7 (o group of 4)
    const int tc = tid & 31;   // 0..31 (m group of 4)

    float acc[4][4];
#pragma unroll
    for (int i = 0; i < 4; i++) {
        float bia = d_ball[o0 + tr * 4 + i];
#pragma unroll
        for (int j = 0; j < 4; j++) acc[i][j] = bia;
    }

    const float* xb = x + (size_t)b * CIN * HW_;

    for (int kc = 0; kc < CIN; kc += 32) {
#pragma unroll
        for (int t = tid; t < 1024; t += 256) {
            int i = t >> 5, j = t & 31;
            Ws[j][i] = d_Wall[(o0 + i) * CIN + kc + j];
        }
#pragma unroll
        for (int t = tid; t < 4096; t += 256) {
            int j = t >> 7, mm = t & 127;
            Xs[j][mm] = xb[(size_t)(kc + j) * HW_ + m0 + mm];
        }
        __syncthreads();
#pragma unroll
        for (int kk = 0; kk < 32; kk++) {
            float4 wv = *(const float4*)&Ws[kk][tr * 4];
            float4 xv = *(const float4*)&Xs[kk][tc * 4];
            acc[0][0] += wv.x * xv.x; acc[0][1] += wv.x * xv.y; acc[0][2] += wv.x * xv.z; acc[0][3] += wv.x * xv.w;
            acc[1][0] += wv.y * xv.x; acc[1][1] += wv.y * xv.y; acc[1][2] += wv.y * xv.z; acc[1][3] += wv.y * xv.w;
            acc[2][0] += wv.z * xv.x; acc[2][1] += wv.z * xv.y; acc[2][2] += wv.z * xv.z; acc[2][3] += wv.z * xv.w;
            acc[3][0] += wv.w * xv.x; acc[3][1] += wv.w * xv.y; acc[3][2] += wv.w * xv.z; acc[3][3] += wv.w * xv.w;
        }
        __syncthreads();
    }

#pragma unroll
    for (int i = 0; i < 4; i++) {
        int o = o0 + tr * 4 + i;
#pragma unroll
        for (int j = 0; j < 4; j++) {
            int m = m0 + tc * 4 + j;
            float v = acc[i][j];
            if (o < DQK)            d_fbuf[((size_t)b * DQK + o) * HW_ + m] = v;
            else if (o < 2 * DQK)   d_gbuf[((size_t)b * DQK + (o - DQK)) * HW_ + m] = v;
            else                    d_hhT[((size_t)b * HW_ + m) * CIN + (o - 2 * DQK)] = v;
        }
    }
}

// -------- flash attention + residual (f32x2 / FFMA2 core) --------
// grid: (HW/64, B); block: 256.
// Scoring mapping: qs = tid>>2 (query), cs = tid&3 (16 keys each).
// PV mapping:      up = tid>>3 (query pair 2up,2up+1), cg = tid&7 (32 channels).
// smem floats: Ks[16*64]=1024 | Ps[64*68]=4352 | Cs[64] | Vs[64*256]=16384
#define PS_STRIDE 68
#define SM_KS 0
#define SM_PS 1024
#define SM_CS (1024 + 64 * PS_STRIDE)
#define SM_VS (SM_CS + 64)
#define ATTN_SMEM_FLOATS (SM_VS + 64 * 256)
#define ATTN_SMEM_BYTES (ATTN_SMEM_FLOATS * 4)

__global__ __launch_bounds__(256, 2) void attn_kernel(const float* __restrict__ x,
                                                      const float* __restrict__ gamma_p,
                                                      float* __restrict__ out) {
    extern __shared__ float sm[];
    float* Ks = sm + SM_KS;
    float* Ps = sm + SM_PS;
    float* Cs = sm + SM_CS;
    float* Vs = sm + SM_VS;

    const int b  = blockIdx.y;
    const int n0 = blockIdx.x * 64;
    const int tid = threadIdx.x;
    // scoring ids
    const int qs = tid >> 2, cs = tid & 3;
    // PV ids
    const int up = tid >> 3, cg = tid & 7;
    const int q0 = up * 2, q1 = q0 + 1;

    // query vector (16) for scoring
    float qr[DQK];
    {
        const float* gq = d_gbuf + (size_t)b * DQK * HW_ + n0 + qs;
#pragma unroll
        for (int k = 0; k < DQK; k++) qr[k] = gq[(size_t)k * HW_];
    }

    u64 acc[2][16];
#pragma unroll
    for (int t = 0; t < 16; t++) { acc[0][t] = 0ull; acc[1][t] = 0ull; }
    float row_max = -1e30f, row_sum = 0.f;

    const float* fb = d_fbuf + (size_t)b * DQK * HW_;
    const float* vb = d_hhT + (size_t)b * HW_ * CIN;

    for (int m0 = 0; m0 < HW_; m0 += 64) {
        __syncthreads();  // previous tile fully consumed
        // load K tile [16][64]
#pragma unroll
        for (int t = tid; t < 1024; t += 256)
            Ks[t] = fb[(size_t)(t >> 6) * HW_ + m0 + (t & 63)];
        // load V tile [64][256]
        {
            const float4* vsrc = (const float4*)(vb + (size_t)m0 * CIN);
            float4* vdst = (float4*)Vs;
#pragma unroll
            for (int t = tid; t < 4096; t += 256) vdst[t] = vsrc[t];
        }
        __syncthreads();

        // ---- scoring: thread (qs, cs) scores keys m = cs*16 + [0,16) ----
        u64 sv2[8];
#pragma unroll
        for (int t = 0; t < 8; t++) sv2[t] = 0ull;
#pragma unroll
        for (int k = 0; k < DQK; k++) {
            const ulonglong2* kk = (const ulonglong2*)(Ks + k * 64 + cs * 16);
            ulonglong2 k0 = kk[0], k1 = kk[1];
            u64 qq; uint32_t qi = __float_as_uint(qr[k]);
            PACK2(qq, qi, qi);
            FMA2(sv2[0], k0.x, qq, sv2[0]); FMA2(sv2[1], k0.y, qq, sv2[1]);
            FMA2(sv2[2], k1.x, qq, sv2[2]); FMA2(sv2[3], k1.y, qq, sv2[3]);
            kk = (const ulonglong2*)(Ks + k * 64 + cs * 16 + 8);
            ulonglong2 k2 = kk[0], k3 = kk[1];
            FMA2(sv2[4], k2.x, qq, sv2[4]); FMA2(sv2[5], k2.y, qq, sv2[5]);
            FMA2(sv2[6], k3.x, qq, sv2[6]); FMA2(sv2[7], k3.y, qq, sv2[7]);
        }
        float s[16];
#pragma unroll
        for (int t = 0; t < 8; t++) {
            uint32_t lo, hi;
            UNPACK2(lo, hi, sv2[t]);
            s[2 * t] = __uint_as_float(lo);
            s[2 * t + 1] = __uint_as_float(hi);
        }
        float tmax = s[0];
#pragma unroll
        for (int t = 1; t < 16; t++) tmax = fmaxf(tmax, s[t]);
        tmax = fmaxf(tmax, __shfl_xor_sync(0xffffffffu, tmax, 1));
        tmax = fmaxf(tmax, __shfl_xor_sync(0xffffffffu, tmax, 2));
        float nmax = fmaxf(row_max, tmax);
        float corr = __expf(row_max - nmax);
        if (cs == 0) Cs[qs] = corr;
        float lsum = 0.f;
#pragma unroll
        for (int j = 0; j < 4; j++) {
            float4 p4;
            p4.x = __expf(s[4 * j + 0] - nmax);
            p4.y = __expf(s[4 * j + 1] - nmax);
            p4.z = __expf(s[4 * j + 2] - nmax);
            p4.w = __expf(s[4 * j + 3] - nmax);
            lsum += p4.x + p4.y + p4.z + p4.w;
            *(float4*)&Ps[qs * PS_STRIDE + cs * 16 + 4 * j] = p4;
        }
        lsum += __shfl_xor_sync(0xffffffffu, lsum, 1);
        lsum += __shfl_xor_sync(0xffffffffu, lsum, 2);
        row_sum = row_sum * corr + lsum;
        row_max = nmax;
        __syncthreads();  // Ps, Cs visible

        // ---- PV: thread (up, cg) accumulates queries q0,q1 x 32 channels ----
        {
            float c0 = Cs[q0], c1 = Cs[q1];
            u64 cc0, cc1;
            uint32_t c0i = __float_as_uint(c0), c1i = __float_as_uint(c1);
            PACK2(cc0, c0i, c0i);
            PACK2(cc1, c1i, c1i);
#pragma unroll
            for (int t = 0; t < 16; t++) {
                MUL2(acc[0][t], acc[0][t], cc0);
                MUL2(acc[1][t], acc[1][t], cc1);
            }
            const float* p0row = Ps + q0 * PS_STRIDE;
            const float* p1row = Ps + q1 * PS_STRIDE;
#pragma unroll 2
            for (int i = 0; i < 64; i++) {
                uint32_t p0i = __float_as_uint(p0row[i]);
                uint32_t p1i = __float_as_uint(p1row[i]);
                u64 pp0, pp1;
                PACK2(pp0, p0i, p0i);
                PACK2(pp1, p1i, p1i);
                const ulonglong2* v2 = (const ulonglong2*)(Vs + i * 256);
#pragma unroll
                for (int j = 0; j < 8; j++) {
                    ulonglong2 v = v2[j * 8 + cg];   // conflict-free: bank group = cg
                    FMA2(acc[0][2 * j],     v.x, pp0, acc[0][2 * j]);
                    FMA2(acc[0][2 * j + 1], v.y, pp0, acc[0][2 * j + 1]);
                    FMA2(acc[1][2 * j],     v.x, pp1, acc[1][2 * j]);
                    FMA2(acc[1][2 * j + 1], v.y, pp1, acc[1][2 * j + 1]);
                }
            }
        }
    }

    // ---- publish row sums (reuse Cs), then epilogue ----
    __syncthreads();
    if (cs == 0) Cs[qs] = row_sum;
    __syncthreads();

    const float gm = *gamma_p;
    const float g0 = gm / Cs[q0];
    const float g1 = gm / Cs[q1];
    const float* xb = x + (size_t)b * CIN * HW_;
    float* ob = out + (size_t)b * CIN * HW_;
    const int n_0 = n0 + q0, n_1 = n0 + q1;
#pragma unroll
    for (int j = 0; j < 8; j++) {
        int cbase = (j * 8 + cg) * 4;
        uint32_t lo, hi;
        UNPACK2(lo, hi, acc[0][2 * j]);
        ob[(size_t)(cbase + 0) * HW_ + n_0] = g0 * __uint_as_float(lo) + xb[(size_t)(cbase + 0) * HW_ + n_0];
        ob[(size_t)(cbase + 1) * HW_ + n_0] = g0 * __uint_as_float(hi) + xb[(size_t)(cbase + 1) * HW_ + n_0];
        UNPACK2(lo, hi, acc[0][2 * j + 1]);
        ob[(size_t)(cbase + 2) * HW_ + n_0] = g0 * __uint_as_float(lo) + xb[(size_t)(cbase + 2) * HW_ + n_0];
        ob[(size_t)(cbase + 3) * HW_ + n_0] = g0 * __uint_as_float(hi) + xb[(size_t)(cbase + 3) * HW_ + n_0];
        UNPACK2(lo, hi, acc[1][2 * j]);
        ob[(size_t)(cbase + 0) * HW_ + n_1] = g1 * __uint_as_float(lo) + xb[(size_t)(cbase + 0) * HW_ + n_1];
        ob[(size_t)(cbase + 1) * HW_ + n_1] = g1 * __uint_as_float(hi) + xb[(size_t)(cbase + 1) * HW_ + n_1];
        UNPACK2(lo, hi, acc[1][2 * j + 1]);
        ob[(size_t)(cbase + 2) * HW_ + n_1] = g1 * __uint_as_float(lo) + xb[(size_t)(cbase + 2) * HW_ + n_1];
        ob[(size_t)(cbase + 3) * HW_ + n_1] = g1 * __uint_as_float(hi) + xb[(size_t)(cbase + 3) * HW_ + n_1];
    }
}

extern "C" void kernel_launch(void* const* d_in, const int* in_sizes, int n_in,
                              void* d_out, int out_size) {
    const float* x  = (const float*)d_in[0];
    const float* Wf = (const float*)d_in[1];
    const float* bf = (const float*)d_in[2];
    const float* Wg = (const float*)d_in[3];
    const float* bg = (const float*)d_in[4];
    const float* Wh = (const float*)d_in[5];
    const float* bh = (const float*)d_in[6];
    const float* gamma = (const float*)d_in[7];
    float* out = (float*)d_out;

    prep_kernel<<<(CIN * CIN + 255) / 256, 256>>>(Wf, bf, Wg, bg, Wh, bh);
    proj_kernel<<<dim3(HW_ / 128, NO_ / 32, B_), 256>>>(x);

    cudaFuncSetAttribute(attn_kernel, cudaFuncAttributeMaxDynamicSharedMemorySize,
                         ATTN_SMEM_BYTES);
    attn_kernel<<<dim3(HW_ / 64, B_), 256, ATTN_SMEM_BYTES>>>(x, gamma, out);
}

// round 4
// speedup vs baseline: 8.0252x; 4.6573x over previous
#include <cuda_runtime.h>
#include <cuda_bf16.h>
#include <cstdint>

#define B_   8
#define CIN  256
#define HW_  4096
#define DQK  16
#define NO_  288
#define L2E  1.4426950408889634f

typedef unsigned long long u64;

// ---------------- portable PTX helpers (NO 'a'-features) ----------------
#define FMA2(d, a, b, c) asm("fma.rn.f32x2 %0, %1, %2, %3;" : "=l"(d) : "l"(a), "l"(b), "l"(c))
#define PACK2(d, lo, hi) asm("mov.b64 %0, {%1, %2};"        : "=l"(d) : "r"(lo), "r"(hi))
#define UNPACK2(lo, hi, s) asm("mov.b64 {%0, %1}, %2;"      : "=r"(lo), "=r"(hi) : "l"(s))

__device__ __forceinline__ uint32_t smem_u32(const void* p) {
    uint32_t a;
    asm("{ .reg .u64 t; cvta.to.shared.u64 t, %1; cvt.u32.u64 %0, t; }" : "=r"(a) : "l"(p));
    return a;
}
__device__ __forceinline__ uint32_t f2tf32(float v) {
    uint32_t h; asm("cvt.rna.tf32.f32 %0, %1;" : "=r"(h) : "f"(v)); return h;
}
__device__ __forceinline__ float ex2(float v) {
    float r; asm("ex2.approx.f32 %0, %1;" : "=f"(r) : "f"(v)); return r;
}
__device__ __forceinline__ uint32_t lds32(uint32_t a) {
    uint32_t v; asm volatile("ld.shared.b32 %0, [%1];" : "=r"(v) : "r"(a)); return v;
}
__device__ __forceinline__ void lds64(uint32_t& x, uint32_t& y, uint32_t a) {
    asm volatile("ld.shared.v2.b32 {%0, %1}, [%2];" : "=r"(x), "=r"(y) : "r"(a));
}
__device__ __forceinline__ void sts32(uint32_t a, uint32_t v) {
    asm volatile("st.shared.b32 [%0], %1;" :: "r"(a), "r"(v));
}
#define CP16(dst, src) asm volatile("cp.async.cg.shared.global [%0], [%1], 16;" :: "r"(dst), "l"(src))
#define CP_COMMIT()    asm volatile("cp.async.commit_group;" ::: "memory")
#define CP_WAIT0()     asm volatile("cp.async.wait_group 0;" ::: "memory")

// mma.sync m16n8k8 tf32 (sm_80+ portable)
__device__ __forceinline__ void mma_acc(float* d, const uint32_t* a, uint32_t b0, uint32_t b1) {
    asm volatile("mma.sync.aligned.m16n8k8.row.col.f32.tf32.tf32.f32 "
        "{%0,%1,%2,%3}, {%4,%5,%6,%7}, {%8,%9}, {%0,%1,%2,%3};"
        : "+f"(d[0]), "+f"(d[1]), "+f"(d[2]), "+f"(d[3])
        : "r"(a[0]), "r"(a[1]), "r"(a[2]), "r"(a[3]), "r"(b0), "r"(b1));
}
__device__ __forceinline__ void mma_zro(float* d, const uint32_t* a, uint32_t b0, uint32_t b1) {
    float z = 0.f;
    asm volatile("mma.sync.aligned.m16n8k8.row.col.f32.tf32.tf32.f32 "
        "{%0,%1,%2,%3}, {%4,%5,%6,%7}, {%8,%9}, {%10,%10,%10,%10};"
        : "=f"(d[0]), "=f"(d[1]), "=f"(d[2]), "=f"(d[3])
        : "r"(a[0]), "r"(a[1]), "r"(a[2]), "r"(a[3]), "r"(b0), "r"(b1), "f"(z));
}

// ---------------- scratch ----------------
__device__ float d_fbuf[B_ * DQK * HW_];         // f [b][k][m]
__device__ float d_gbuf[B_ * DQK * HW_];         // g [b][k][n]
__device__ float d_fhi[B_ * DQK * HW_];          // tf32-hi of f
__device__ float d_flo[B_ * DQK * HW_];          // residual of f
__device__ float d_hh[(size_t)B_ * CIN * HW_];   // h [b][c][m']  (m permuted within 8-groups)
__device__ float d_Wall[NO_ * CIN];
__device__ float d_ball[NO_];
__device__ float d_fmax2[B_];

// ---------------- prep ----------------
__global__ void prep_kernel(const float* __restrict__ Wf, const float* __restrict__ bf,
                            const float* __restrict__ Wg, const float* __restrict__ bg,
                            const float* __restrict__ Wh, const float* __restrict__ bh) {
    int i = blockIdx.x * blockDim.x + threadIdx.x;
    if (i < DQK * CIN) { d_Wall[i] = Wf[i]; d_Wall[DQK * CIN + i] = Wg[i]; }
    if (i < CIN * CIN) d_Wall[2 * DQK * CIN + i] = Wh[i];
    if (i < DQK) { d_ball[i] = bf[i]; d_ball[DQK + i] = bg[i]; }
    if (i < CIN) d_ball[2 * DQK + i] = bh[i];
    if (i < B_)  d_fmax2[i] = 0.f;
}

// ---------------- projection GEMM (f32x2 inner) ----------------
__global__ __launch_bounds__(256) void proj_kernel(const float* __restrict__ x) {
    const int b  = blockIdx.z;
    const int o0 = blockIdx.y * 32;
    const int m0 = blockIdx.x * 128;

    __shared__ float Ws[32][36];
    __shared__ float Xs[32][128];

    const int tid = threadIdx.x;
    const int tr = tid >> 5, tc = tid & 31;

    u64 acc2[4][2];
#pragma unroll
    for (int i = 0; i < 4; i++) {
        uint32_t bi = __float_as_uint(d_ball[o0 + tr * 4 + i]);
        PACK2(acc2[i][0], bi, bi);
        PACK2(acc2[i][1], bi, bi);
    }

    const float* xb = x + (size_t)b * CIN * HW_;

    for (int kc = 0; kc < CIN; kc += 32) {
#pragma unroll
        for (int t = tid; t < 1024; t += 256) {
            int i = t >> 5, j = t & 31;
            Ws[j][i] = d_Wall[(o0 + i) * CIN + kc + j];
        }
#pragma unroll
        for (int t = tid; t < 4096; t += 256) {
            int j = t >> 7, mm = t & 127;
            Xs[j][mm] = xb[(size_t)(kc + j) * HW_ + m0 + mm];
        }
        __syncthreads();
#pragma unroll
        for (int kk = 0; kk < 32; kk++) {
            float4 wv = *(const float4*)&Ws[kk][tr * 4];
            ulonglong2 xv = *(const ulonglong2*)&Xs[kk][tc * 4];
            u64 w0, w1, w2, w3;
            uint32_t a0 = __float_as_uint(wv.x), a1 = __float_as_uint(wv.y);
            uint32_t a2 = __float_as_uint(wv.z), a3 = __float_as_uint(wv.w);
            PACK2(w0, a0, a0); PACK2(w1, a1, a1); PACK2(w2, a2, a2); PACK2(w3, a3, a3);
            FMA2(acc2[0][0], xv.x, w0, acc2[0][0]); FMA2(acc2[0][1], xv.y, w0, acc2[0][1]);
            FMA2(acc2[1][0], xv.x, w1, acc2[1][0]); FMA2(acc2[1][1], xv.y, w1, acc2[1][1]);
            FMA2(acc2[2][0], xv.x, w2, acc2[2][0]); FMA2(acc2[2][1], xv.y, w2, acc2[2][1]);
            FMA2(acc2[3][0], xv.x, w3, acc2[3][0]); FMA2(acc2[3][1], xv.y, w3, acc2[3][1]);
        }
        __syncthreads();
    }

#pragma unroll
    for (int i = 0; i < 4; i++) {
        int o = o0 + tr * 4 + i;
        float av[4];
        uint32_t lo, hi;
        UNPACK2(lo, hi, acc2[i][0]); av[0] = __uint_as_float(lo); av[1] = __uint_as_float(hi);
        UNPACK2(lo, hi, acc2[i][1]); av[2] = __uint_as_float(lo); av[3] = __uint_as_float(hi);
#pragma unroll
        for (int j = 0; j < 4; j++) {
            int m = m0 + tc * 4 + j;
            float v = av[j];
            if (o < DQK)            d_fbuf[((size_t)b * DQK + o) * HW_ + m] = v;
            else if (o < 2 * DQK)   d_gbuf[((size_t)b * DQK + (o - DQK)) * HW_ + m] = v;
            else {
                // key-permuted store: within each 8-group, pos(e) = 2*(e&3) | (e>>2)
                int mp = (m & ~7) | ((j << 1) | (tc & 1));
                d_hh[((size_t)b * CIN + (o - 2 * DQK)) * HW_ + mp] = v;
            }
        }
    }
}

// ---------------- f row-norm max + tf32 hi/lo split ----------------
__global__ void fmax_kernel() {
    int b = blockIdx.y;
    int m = blockIdx.x * 256 + threadIdx.x;
    const float* fb = d_fbuf + (size_t)b * DQK * HW_;
    float* fh = d_fhi + (size_t)b * DQK * HW_;
    float* fl = d_flo + (size_t)b * DQK * HW_;
    float s = 0.f;
#pragma unroll
    for (int k = 0; k < DQK; k++) {
        float v = fb[(size_t)k * HW_ + m];
        s = fmaf(v, v, s);
        uint32_t h = f2tf32(v);
        fh[(size_t)k * HW_ + m] = __uint_as_float(h);
        fl[(size_t)k * HW_ + m] = v - __uint_as_float(h);
    }
#pragma unroll
    for (int o = 16; o; o >>= 1) s = fmaxf(s, __shfl_xor_sync(0xffffffffu, s, o));
    __shared__ float red[8];
    if ((threadIdx.x & 31) == 0) red[threadIdx.x >> 5] = s;
    __syncthreads();
    if (threadIdx.x == 0) {
        float mx = red[0];
#pragma unroll
        for (int w = 1; w < 8; w++) mx = fmaxf(mx, red[w]);
        atomicMax((unsigned int*)&d_fmax2[b], __float_as_uint(mx));
    }
}

// ---------------- mma.sync flash attention ----------------
// smem (bytes): F0@0 F1@9216 (32 rows x 72 floats: hi rows 0-15, lo rows 16-31)
//               V0@18432 V1@92160 (256 ch x 72 floats, key-permuted cols)
//               P @165888 (128 q x 72 floats, key-permuted cols)
#define ROWB 288              // 72 floats * 4
#define OFF_F0 0
#define OFF_F1 9216
#define OFF_V0 18432
#define OFF_V1 92160
#define OFF_P  165888
#define SMEM_BYTES 202752

__device__ __forceinline__ void load_tile_async(uint32_t sb, int buf,
                                                const float* fhib, const float* flob,
                                                const float* vb, int m0, int tid) {
    uint32_t fdst = sb + (buf ? OFF_F1 : OFF_F0);
    int k = tid >> 4, j = tid & 15;
    CP16(fdst + k * ROWB + j * 16, fhib + (size_t)k * HW_ + m0 + j * 4);
    CP16(fdst + (k + 16) * ROWB + j * 16, flob + (size_t)k * HW_ + m0 + j * 4);
    uint32_t vdst = sb + (buf ? OFF_V1 : OFF_V0);
#pragma unroll
    for (int i = 0; i < 16; i++) {
        int id = tid + 256 * i;
        int c = id >> 4, jj = id & 15;
        CP16(vdst + c * ROWB + jj * 16, vb + (size_t)c * HW_ + m0 + jj * 4);
    }
    CP_COMMIT();
}

__global__ __launch_bounds__(256, 1) void attn_kernel(const float* __restrict__ x,
                                                      const float* __restrict__ gamma_p,
                                                      float* __restrict__ out) {
    extern __shared__ char smraw[];
    const uint32_t sb = smem_u32(smraw);
    const int tid = threadIdx.x, wid = tid >> 5, lane = tid & 31;
    const int t4 = lane & 3, r4 = lane >> 2;
    const int b = blockIdx.y, n0 = blockIdx.x * 128;

    const float* gb   = d_gbuf + (size_t)b * DQK * HW_;
    const float* fhib = d_fhi + (size_t)b * DQK * HW_;
    const float* flob = d_flo + (size_t)b * DQK * HW_;
    const float* vb   = d_hh  + (size_t)b * CIN * HW_;

    // ---- Q fragments (hi/lo), row bounds ----
    uint32_t qh[2][4], ql[2][4];
    float q2a = 0.f, q2b = 0.f;
#pragma unroll
    for (int ks = 0; ks < 2; ks++) {
#pragma unroll
        for (int h = 0; h < 2; h++) {
            int k = ks * 8 + t4 + h * 4;
            float va = gb[(size_t)k * HW_ + n0 + wid * 16 + r4];
            float vbq = gb[(size_t)k * HW_ + n0 + wid * 16 + r4 + 8];
            q2a = fmaf(va, va, q2a);
            q2b = fmaf(vbq, vbq, q2b);
            uint32_t ha = f2tf32(va), hb = f2tf32(vbq);
            qh[ks][h * 2]     = ha;
            qh[ks][h * 2 + 1] = hb;
            ql[ks][h * 2]     = __float_as_uint(va - __uint_as_float(ha));
            ql[ks][h * 2 + 1] = __float_as_uint(vbq - __uint_as_float(hb));
        }
    }
    q2a = fmaxf(q2a, 0.f) ;
    q2a += __shfl_xor_sync(0xffffffffu, q2a, 1); q2a += __shfl_xor_sync(0xffffffffu, q2a, 2);
    q2b += __shfl_xor_sync(0xffffffffu, q2b, 1); q2b += __shfl_xor_sync(0xffffffffu, q2b, 2);
    const float fm = sqrtf(d_fmax2[b]);
    const float negml2_a = -sqrtf(q2a) * fm * L2E;
    const float negml2_b = -sqrtf(q2b) * fm * L2E;

    float acc[32][4];
#pragma unroll
    for (int nt = 0; nt < 32; nt++) { acc[nt][0] = acc[nt][1] = acc[nt][2] = acc[nt][3] = 0.f; }
    float rs_a = 0.f, rs_b = 0.f;

    // P layout constants (key-permuted columns)
    const int e0 = 2 * t4, e1 = e0 + 1;
    const int p0 = ((e0 & 3) << 1) | (e0 >> 2);
    const int p1 = ((e1 & 3) << 1) | (e1 >> 2);
    const uint32_t prow_a = sb + OFF_P + (wid * 16 + r4) * ROWB;
    const uint32_t prow_b = prow_a + 8 * ROWB;

    load_tile_async(sb, 0, fhib, flob, vb, 0, tid);

    for (int i = 0; i < 64; i++) {
        const int buf = i & 1;
        CP_WAIT0();
        __syncthreads();
        if (i < 63) load_tile_async(sb, buf ^ 1, fhib, flob, vb, (i + 1) * 64, tid);

        const uint32_t fbase = sb + (buf ? OFF_F1 : OFF_F0);
        // ---- QK (tf32 x3) ----
        float s[8][4];
#pragma unroll
        for (int ks = 0; ks < 2; ks++) {
#pragma unroll
            for (int nt = 0; nt < 8; nt++) {
                uint32_t a0 = fbase + (ks * 8 + t4) * ROWB + (nt * 8 + r4) * 4;
                uint32_t bh0 = lds32(a0), bh1 = lds32(a0 + 4 * ROWB);
                if (ks == 0) mma_zro(s[nt], qh[0], bh0, bh1);
                else         mma_acc(s[nt], qh[1], bh0, bh1);
                mma_acc(s[nt], ql[ks], bh0, bh1);
            }
#pragma unroll
            for (int nt = 0; nt < 8; nt++) {
                uint32_t a0 = fbase + (16 + ks * 8 + t4) * ROWB + (nt * 8 + r4) * 4;
                uint32_t bl0 = lds32(a0), bl1 = lds32(a0 + 4 * ROWB);
                mma_acc(s[nt], qh[ks], bl0, bl1);
            }
        }
        // ---- softmax (bound-based, no rescale) + store P ----
#pragma unroll
        for (int nt = 0; nt < 8; nt++) {
            float pa0 = ex2(fmaf(s[nt][0], L2E, negml2_a));
            float pa1 = ex2(fmaf(s[nt][1], L2E, negml2_a));
            float pb0 = ex2(fmaf(s[nt][2], L2E, negml2_b));
            float pb1 = ex2(fmaf(s[nt][3], L2E, negml2_b));
            rs_a += pa0 + pa1;
            rs_b += pb0 + pb1;
            sts32(prow_a + (nt * 8 + p0) * 4, f2tf32(pa0));
            sts32(prow_a + (nt * 8 + p1) * 4, f2tf32(pa1));
            sts32(prow_b + (nt * 8 + p0) * 4, f2tf32(pb0));
            sts32(prow_b + (nt * 8 + p1) * 4, f2tf32(pb1));
        }
        __syncwarp();

        // ---- PV ----
        uint32_t A[8][4];
#pragma unroll
        for (int ks = 0; ks < 8; ks++) {
            lds64(A[ks][0], A[ks][2], prow_a + (ks * 8 + 2 * t4) * 4);
            lds64(A[ks][1], A[ks][3], prow_b + (ks * 8 + 2 * t4) * 4);
        }
        const uint32_t vbase = sb + (buf ? OFF_V1 : OFF_V0) + r4 * ROWB + t4 * 8;
#pragma unroll
        for (int ks = 0; ks < 8; ks++) {
#pragma unroll
            for (int nt = 0; nt < 32; nt++) {
                uint32_t b0, b1;
                lds64(b0, b1, vbase + nt * 8 * ROWB + ks * 32);
                mma_acc(acc[nt], A[ks], b0, b1);
            }
        }
        __syncwarp();
    }

    // ---- epilogue ----
    rs_a += __shfl_xor_sync(0xffffffffu, rs_a, 1); rs_a += __shfl_xor_sync(0xffffffffu, rs_a, 2);
    rs_b += __shfl_xor_sync(0xffffffffu, rs_b, 1); rs_b += __shfl_xor_sync(0xffffffffu, rs_b, 2);
    const float gm = *gamma_p;
    const float inv_a = gm / rs_a, inv_b = gm / rs_b;
    const float* xb = x + (size_t)b * CIN * HW_;
    float* ob = out + (size_t)b * CIN * HW_;
    const int na = n0 + wid * 16 + r4, nb = na + 8;
#pragma unroll
    for (int nt = 0; nt < 32; nt++) {
        int ch0 = nt * 8 + 2 * t4, ch1 = ch0 + 1;
        ob[(size_t)ch0 * HW_ + na] = fmaf(inv_a, acc[nt][0], xb[(size_t)ch0 * HW_ + na]);
        ob[(size_t)ch1 * HW_ + na] = fmaf(inv_a, acc[nt][1], xb[(size_t)ch1 * HW_ + na]);
        ob[(size_t)ch0 * HW_ + nb] = fmaf(inv_b, acc[nt][2], xb[(size_t)ch0 * HW_ + nb]);
        ob[(size_t)ch1 * HW_ + nb] = fmaf(inv_b, acc[nt][3], xb[(size_t)ch1 * HW_ + nb]);
    }
}

// ---------------- launch ----------------
extern "C" void kernel_launch(void* const* d_in, const int* in_sizes, int n_in,
                              void* d_out, int out_size) {
    const float* x  = (const float*)d_in[0];
    const float* Wf = (const float*)d_in[1];
    const float* bf = (const float*)d_in[2];
    const float* Wg = (const float*)d_in[3];
    const float* bg = (const float*)d_in[4];
    const float* Wh = (const float*)d_in[5];
    const float* bh = (const float*)d_in[6];
    const float* gamma = (const float*)d_in[7];
    float* out = (float*)d_out;

    prep_kernel<<<(CIN * CIN + 255) / 256, 256>>>(Wf, bf, Wg, bg, Wh, bh);
    proj_kernel<<<dim3(HW_ / 128, NO_ / 32, B_), 256>>>(x);
    fmax_kernel<<<dim3(HW_ / 256, B_), 256>>>();

    cudaFuncSetAttribute(attn_kernel, cudaFuncAttributeMaxDynamicSharedMemorySize, SMEM_BYTES);
    attn_kernel<<<dim3(HW_ / 128, B_), 256, SMEM_BYTES>>>(x, gamma, out);
}

// round 6
// speedup vs baseline: 9.4060x; 1.1721x over previous
#include <cuda_runtime.h>
#include <cuda_bf16.h>
#include <cuda_fp16.h>
#include <cstdint>

#define B_   8
#define CIN  256
#define HW_  4096
#define DQK  16
#define NO_  288
#define L2E  1.4426950408889634f
#define PSHIFT 10.0f

typedef unsigned long long u64;

// ---------------- portable PTX helpers ----------------
#define FMA2(d, a, b, c) asm("fma.rn.f32x2 %0, %1, %2, %3;" : "=l"(d) : "l"(a), "l"(b), "l"(c))
#define PACK2(d, lo, hi) asm("mov.b64 %0, {%1, %2};"        : "=l"(d) : "r"(lo), "r"(hi))
#define UNPACK2(lo, hi, s) asm("mov.b64 {%0, %1}, %2;"      : "=r"(lo), "=r"(hi) : "l"(s))

__device__ __forceinline__ uint32_t smem_u32(const void* p) {
    uint32_t a;
    asm("{ .reg .u64 t; cvta.to.shared.u64 t, %1; cvt.u32.u64 %0, t; }" : "=r"(a) : "l"(p));
    return a;
}
__device__ __forceinline__ uint32_t f2tf32(float v) {
    uint32_t h; asm("cvt.rna.tf32.f32 %0, %1;" : "=r"(h) : "f"(v)); return h;
}
__device__ __forceinline__ float ex2(float v) {
    float r; asm("ex2.approx.f32 %0, %1;" : "=f"(r) : "f"(v)); return r;
}
__device__ __forceinline__ uint32_t pack_h2(float lo, float hi) {
    uint32_t d; asm("cvt.rn.f16x2.f32 %0, %1, %2;" : "=r"(d) : "f"(hi), "f"(lo)); return d;
}
__device__ __forceinline__ uint32_t lds32(uint32_t a) {
    uint32_t v; asm volatile("ld.shared.b32 %0, [%1];" : "=r"(v) : "r"(a)); return v;
}
__device__ __forceinline__ void lds64(uint32_t& x, uint32_t& y, uint32_t a) {
    asm volatile("ld.shared.v2.b32 {%0, %1}, [%2];" : "=r"(x), "=r"(y) : "r"(a));
}
__device__ __forceinline__ void sts32(uint32_t a, uint32_t v) {
    asm volatile("st.shared.b32 [%0], %1;" :: "r"(a), "r"(v));
}
#define CP16(dst, src) asm volatile("cp.async.cg.shared.global [%0], [%1], 16;" :: "r"(dst), "l"(src))
#define CP_COMMIT()    asm volatile("cp.async.commit_group;" ::: "memory")
#define CP_WAIT0()     asm volatile("cp.async.wait_group 0;" ::: "memory")

// mma.sync tf32 m16n8k8
__device__ __forceinline__ void mma_acc(float* d, const uint32_t* a, uint32_t b0, uint32_t b1) {
    asm volatile("mma.sync.aligned.m16n8k8.row.col.f32.tf32.tf32.f32 "
        "{%0,%1,%2,%3}, {%4,%5,%6,%7}, {%8,%9}, {%0,%1,%2,%3};"
        : "+f"(d[0]), "+f"(d[1]), "+f"(d[2]), "+f"(d[3])
        : "r"(a[0]), "r"(a[1]), "r"(a[2]), "r"(a[3]), "r"(b0), "r"(b1));
}
__device__ __forceinline__ void mma_zro(float* d, const uint32_t* a, uint32_t b0, uint32_t b1) {
    float z = 0.f;
    asm volatile("mma.sync.aligned.m16n8k8.row.col.f32.tf32.tf32.f32 "
        "{%0,%1,%2,%3}, {%4,%5,%6,%7}, {%8,%9}, {%10,%10,%10,%10};"
        : "=f"(d[0]), "=f"(d[1]), "=f"(d[2]), "=f"(d[3])
        : "r"(a[0]), "r"(a[1]), "r"(a[2]), "r"(a[3]), "r"(b0), "r"(b1), "f"(z));
}
// mma.sync fp16 m16n8k16 (fp32 accum)
__device__ __forceinline__ void mma_h16(float* d, const uint32_t* a, uint32_t b0, uint32_t b1) {
    asm volatile("mma.sync.aligned.m16n8k16.row.col.f32.f16.f16.f32 "
        "{%0,%1,%2,%3}, {%4,%5,%6,%7}, {%8,%9}, {%0,%1,%2,%3};"
        : "+f"(d[0]), "+f"(d[1]), "+f"(d[2]), "+f"(d[3])
        : "r"(a[0]), "r"(a[1]), "r"(a[2]), "r"(a[3]), "r"(b0), "r"(b1));
}

// key permutation within 16-groups for fp16 frag-contiguous loads
__device__ __forceinline__ int kperm(int e) {
    return (((e & 7) >> 1) << 2) | (e & 1) | ((e >> 3) << 1);
}

// ---------------- scratch ----------------
__device__ float  d_gbuf[B_ * DQK * HW_];
__device__ float  d_fhi[B_ * DQK * HW_];
__device__ float  d_flo[B_ * DQK * HW_];
__device__ __half d_hh[(size_t)B_ * CIN * HW_];   // V fp16, key-permuted within 16-groups
__device__ float  d_Wall[NO_ * CIN];
__device__ float  d_ball[NO_];

// ---------------- prep ----------------
__global__ void prep_kernel(const float* __restrict__ Wf, const float* __restrict__ bf,
                            const float* __restrict__ Wg, const float* __restrict__ bg,
                            const float* __restrict__ Wh, const float* __restrict__ bh) {
    int i = blockIdx.x * blockDim.x + threadIdx.x;
    if (i < DQK * CIN) { d_Wall[i] = Wf[i]; d_Wall[DQK * CIN + i] = Wg[i]; }
    if (i < CIN * CIN) d_Wall[2 * DQK * CIN + i] = Wh[i];
    if (i < DQK) { d_ball[i] = bf[i]; d_ball[DQK + i] = bg[i]; }
    if (i < CIN) d_ball[2 * DQK + i] = bh[i];
}

// ---------------- projection GEMM (f32x2 inner) ----------------
__global__ __launch_bounds__(256) void proj_kernel(const float* __restrict__ x) {
    const int b  = blockIdx.z;
    const int o0 = blockIdx.y * 32;
    const int m0 = blockIdx.x * 128;

    __shared__ float Ws[32][36];
    __shared__ float Xs[32][128];

    const int tid = threadIdx.x;
    const int tr = tid >> 5, tc = tid & 31;

    u64 acc2[4][2];
#pragma unroll
    for (int i = 0; i < 4; i++) {
        uint32_t bi = __float_as_uint(d_ball[o0 + tr * 4 + i]);
        PACK2(acc2[i][0], bi, bi);
        PACK2(acc2[i][1], bi, bi);
    }

    const float* xb = x + (size_t)b * CIN * HW_;

    for (int kc = 0; kc < CIN; kc += 32) {
#pragma unroll
        for (int t = tid; t < 1024; t += 256) {
            int i = t >> 5, j = t & 31;
            Ws[j][i] = d_Wall[(o0 + i) * CIN + kc + j];
        }
#pragma unroll
        for (int t = tid; t < 4096; t += 256) {
            int j = t >> 7, mm = t & 127;
            Xs[j][mm] = xb[(size_t)(kc + j) * HW_ + m0 + mm];
        }
        __syncthreads();
#pragma unroll
        for (int kk = 0; kk < 32; kk++) {
            float4 wv = *(const float4*)&Ws[kk][tr * 4];
            ulonglong2 xv = *(const ulonglong2*)&Xs[kk][tc * 4];
            u64 w0, w1, w2, w3;
            uint32_t a0 = __float_as_uint(wv.x), a1 = __float_as_uint(wv.y);
            uint32_t a2 = __float_as_uint(wv.z), a3 = __float_as_uint(wv.w);
            PACK2(w0, a0, a0); PACK2(w1, a1, a1); PACK2(w2, a2, a2); PACK2(w3, a3, a3);
            FMA2(acc2[0][0], xv.x, w0, acc2[0][0]); FMA2(acc2[0][1], xv.y, w0, acc2[0][1]);
            FMA2(acc2[1][0], xv.x, w1, acc2[1][0]); FMA2(acc2[1][1], xv.y, w1, acc2[1][1]);
            FMA2(acc2[2][0], xv.x, w2, acc2[2][0]); FMA2(acc2[2][1], xv.y, w2, acc2[2][1]);
            FMA2(acc2[3][0], xv.x, w3, acc2[3][0]); FMA2(acc2[3][1], xv.y, w3, acc2[3][1]);
        }
        __syncthreads();
    }

#pragma unroll
    for (int i = 0; i < 4; i++) {
        int o = o0 + tr * 4 + i;
        float av[4];
        uint32_t lo, hi;
        UNPACK2(lo, hi, acc2[i][0]); av[0] = __uint_as_float(lo); av[1] = __uint_as_float(hi);
        UNPACK2(lo, hi, acc2[i][1]); av[2] = __uint_as_float(lo); av[3] = __uint_as_float(hi);
#pragma unroll
        for (int j = 0; j < 4; j++) {
            int m = m0 + tc * 4 + j;
            float v = av[j];
            if (o < DQK) {
                size_t idx = ((size_t)b * DQK + o) * HW_ + m;
                uint32_t h = f2tf32(v);
                d_fhi[idx] = __uint_as_float(h);
                d_flo[idx] = v - __uint_as_float(h);
            } else if (o < 2 * DQK) {
                d_gbuf[((size_t)b * DQK + (o - DQK)) * HW_ + m] = v;
            } else {
                int mp = (m & ~15) | kperm(m & 15);
                d_hh[((size_t)b * CIN + (o - 2 * DQK)) * HW_ + mp] = __float2half_rn(v);
            }
        }
    }
}

// ---------------- mma.sync flash attention (exact-max prepass + tf32x3 QK + fp16 PV) ----------------
// smem: F 32rows x 288B (hi rows0-15, lo 16-31), double-buffered
//       V 256ch x 160B (64 fp16 keys + pad), double-buffered
//       P 128q x 160B; RS 2 x 128 floats (row maxes, then row sums)
#define ROWF 288
#define ROWV 160
#define ROWP 160
#define OFF_F0 0
#define OFF_F1 9216
#define OFF_V0 18432
#define OFF_V1 59392
#define OFF_P  100352
#define OFF_RS 120832
#define SMEM_BYTES 121856

__device__ __forceinline__ void load_tile_async(uint32_t sb, int buf,
                                                const float* fhib, const float* flob,
                                                const __half* vb, int m0, int tid) {
    uint32_t fdst = sb + (buf ? OFF_F1 : OFF_F0);
#pragma unroll
    for (int j = 0; j < 2; j++) {
        int i = tid + 256 * j;
        int row = i >> 4, c = i & 15;
        const float* src = (row < 16) ? (fhib + (size_t)row * HW_ + m0 + c * 4)
                                      : (flob + (size_t)(row - 16) * HW_ + m0 + c * 4);
        CP16(fdst + row * ROWF + c * 16, src);
    }
    uint32_t vdst = sb + (buf ? OFF_V1 : OFF_V0);
#pragma unroll
    for (int j = 0; j < 8; j++) {
        int i = tid + 256 * j;
        int row = i >> 3, c = i & 7;
        CP16(vdst + row * ROWV + c * 16, vb + (size_t)row * HW_ + m0 + c * 8);
    }
    CP_COMMIT();
}

__device__ __forceinline__ void load_f_async(uint32_t sb, int buf,
                                             const float* fhib, int m0, int tid) {
    uint32_t fdst = sb + (buf ? OFF_F1 : OFF_F0);
    int row = tid >> 4, c = tid & 15;   // hi rows only
    CP16(fdst + row * ROWF + c * 16, fhib + (size_t)row * HW_ + m0 + c * 4);
    CP_COMMIT();
}

__global__ __launch_bounds__(256, 1) void attn_kernel(const float* __restrict__ x,
                                                      const float* __restrict__ gamma_p,
                                                      float* __restrict__ out) {
    extern __shared__ char smraw[];
    const uint32_t sb = smem_u32(smraw);
    float* rsm = (float*)(smraw + OFF_RS);
    const int tid = threadIdx.x, wid = tid >> 5, lane = tid & 31;
    const int t4 = lane & 3, r4 = lane >> 2;
    const int qg = wid >> 1, half = wid & 1;
    const int qbase = qg * 32;
    const int b = blockIdx.y, n0 = blockIdx.x * 128;

    const float*  gb   = d_gbuf + (size_t)b * DQK * HW_;
    const float*  fhib = d_fhi + (size_t)b * DQK * HW_;
    const float*  flob = d_flo + (size_t)b * DQK * HW_;
    const __half* vb   = d_hh  + (size_t)b * CIN * HW_;

    // ---- Q fragments (hi/lo) ----
    uint32_t qh[2][2][4], ql[2][2][4];
#pragma unroll
    for (int qt = 0; qt < 2; qt++) {
        const int nq = n0 + qbase + qt * 16 + r4;
#pragma unroll
        for (int ks = 0; ks < 2; ks++) {
#pragma unroll
            for (int h = 0; h < 2; h++) {
                int k = ks * 8 + t4 + h * 4;
                float va = gb[(size_t)k * HW_ + nq];
                float vq = gb[(size_t)k * HW_ + nq + 8];
                uint32_t ha = f2tf32(va), hb = f2tf32(vq);
                qh[qt][ks][h * 2]     = ha;
                qh[qt][ks][h * 2 + 1] = hb;
                ql[qt][ks][h * 2]     = __float_as_uint(va - __uint_as_float(ha));
                ql[qt][ks][h * 2 + 1] = __float_as_uint(vq - __uint_as_float(hb));
            }
        }
    }

    // ================= PREPASS: exact per-row max of S =================
    float smax[2][2] = {{-1e30f, -1e30f}, {-1e30f, -1e30f}};
    load_f_async(sb, 0, fhib, 0, tid);
    for (int i = 0; i < 64; i++) {
        const int buf = i & 1;
        CP_WAIT0();
        __syncthreads();
        if (i < 63) load_f_async(sb, buf ^ 1, fhib, (i + 1) * 64, tid);
        const uint32_t fbase = sb + (buf ? OFF_F1 : OFF_F0);
        const uint32_t keyb  = half * 128 + r4 * 4;
#pragma unroll
        for (int nt = 0; nt < 4; nt++) {
            uint32_t a0 = fbase + t4 * ROWF + keyb + nt * 32;
            uint32_t b0 = lds32(a0), b1 = lds32(a0 + 4 * ROWF);
            uint32_t a1 = a0 + 8 * ROWF;
            uint32_t c0 = lds32(a1), c1 = lds32(a1 + 4 * ROWF);
            float s0[4], s1[4];
            mma_zro(s0, qh[0][0], b0, b1);
            mma_zro(s1, qh[1][0], b0, b1);
            mma_acc(s0, qh[0][1], c0, c1);
            mma_acc(s1, qh[1][1], c0, c1);
            smax[0][0] = fmaxf(smax[0][0], fmaxf(s0[0], s0[1]));
            smax[0][1] = fmaxf(smax[0][1], fmaxf(s0[2], s0[3]));
            smax[1][0] = fmaxf(smax[1][0], fmaxf(s1[0], s1[1]));
            smax[1][1] = fmaxf(smax[1][1], fmaxf(s1[2], s1[3]));
        }
        __syncthreads();
    }
#pragma unroll
    for (int qt = 0; qt < 2; qt++)
#pragma unroll
        for (int j = 0; j < 2; j++) {
            float m = smax[qt][j];
            m = fmaxf(m, __shfl_xor_sync(0xffffffffu, m, 1));
            m = fmaxf(m, __shfl_xor_sync(0xffffffffu, m, 2));
            smax[qt][j] = m;
        }
    if (t4 == 0) {
#pragma unroll
        for (int qt = 0; qt < 2; qt++) {
            rsm[half * 128 + qbase + qt * 16 + r4]     = smax[qt][0];
            rsm[half * 128 + qbase + qt * 16 + r4 + 8] = smax[qt][1];
        }
    }
    __syncthreads();
    float negml[2][2];
#pragma unroll
    for (int qt = 0; qt < 2; qt++) {
        int row = qbase + qt * 16 + r4;
        negml[qt][0] = PSHIFT - fmaxf(rsm[row], rsm[128 + row]) * L2E;
        negml[qt][1] = PSHIFT - fmaxf(rsm[row + 8], rsm[128 + row + 8]) * L2E;
    }

    // ================= MAIN LOOP =================
    float acc[2][16][4];
#pragma unroll
    for (int qt = 0; qt < 2; qt++)
#pragma unroll
        for (int ct = 0; ct < 16; ct++) { acc[qt][ct][0] = acc[qt][ct][1] = acc[qt][ct][2] = acc[qt][ct][3] = 0.f; }
    float rs[2][2] = {{0.f, 0.f}, {0.f, 0.f}};

    const uint32_t pbase = sb + OFF_P + qbase * ROWP;
    const uint32_t poff  = half * 64 + t4 * 8;

    load_tile_async(sb, 0, fhib, flob, vb, 0, tid);

    for (int i = 0; i < 64; i++) {
        const int buf = i & 1;
        CP_WAIT0();
        __syncthreads();                    // tile data ready; P(i-1) consumed
        if (i < 63) load_tile_async(sb, buf ^ 1, fhib, flob, vb, (i + 1) * 64, tid);

        const uint32_t fbase = sb + (buf ? OFF_F1 : OFF_F0);
        const uint32_t keyb  = half * 128 + r4 * 4;

        // ---- QK (tf32 x3): 32 queries x 32 keys per warp ----
        float s[2][4][4];
#pragma unroll
        for (int ks = 0; ks < 2; ks++) {
#pragma unroll
            for (int nt = 0; nt < 4; nt++) {
                uint32_t a0 = fbase + (ks * 8 + t4) * ROWF + keyb + nt * 32;
                uint32_t bh0 = lds32(a0), bh1 = lds32(a0 + 4 * ROWF);
                uint32_t al = a0 + 16 * ROWF;
                uint32_t bl0 = lds32(al), bl1 = lds32(al + 4 * ROWF);
                if (ks == 0) { mma_zro(s[0][nt], qh[0][0], bh0, bh1); mma_zro(s[1][nt], qh[1][0], bh0, bh1); }
                else         { mma_acc(s[0][nt], qh[0][1], bh0, bh1); mma_acc(s[1][nt], qh[1][1], bh0, bh1); }
                mma_acc(s[0][nt], ql[0][ks], bh0, bh1);
                mma_acc(s[1][nt], ql[1][ks], bh0, bh1);
                mma_acc(s[0][nt], qh[0][ks], bl0, bl1);
                mma_acc(s[1][nt], qh[1][ks], bl0, bl1);
            }
        }

        // ---- softmax (exact max, fp16-safe) + store P (fp16, key-permuted) ----
#pragma unroll
        for (int qt = 0; qt < 2; qt++) {
            uint32_t prow = pbase + (qt * 16 + r4) * ROWP;
#pragma unroll
            for (int nt = 0; nt < 4; nt++) {
                float pa0 = ex2(fmaf(s[qt][nt][0], L2E, negml[qt][0]));
                float pa1 = ex2(fmaf(s[qt][nt][1], L2E, negml[qt][0]));
                float pb0 = ex2(fmaf(s[qt][nt][2], L2E, negml[qt][1]));
                float pb1 = ex2(fmaf(s[qt][nt][3], L2E, negml[qt][1]));
                rs[qt][0] += pa0 + pa1;
                rs[qt][1] += pb0 + pb1;
                uint32_t off = poff + (nt >> 1) * 32 + (nt & 1) * 4;
                sts32(prow + off, pack_h2(pa0, pa1));
                sts32(prow + 8 * ROWP + off, pack_h2(pb0, pb1));
            }
        }
        __syncthreads();                    // P visible to partner warp

        // ---- PV (fp16 m16n8k16): 32 queries x 128 channels per warp ----
        const uint32_t vrow = sb + (buf ? OFF_V1 : OFF_V0) + (half * 128 + r4) * ROWV + t4 * 8;
#pragma unroll
        for (int ks = 0; ks < 4; ks++) {
            uint32_t A0[4], A1[4];
            uint32_t pr = pbase + r4 * ROWP + ks * 32 + t4 * 8;
            lds64(A0[0], A0[2], pr);
            lds64(A0[1], A0[3], pr + 8 * ROWP);
            lds64(A1[0], A1[2], pr + 16 * ROWP);
            lds64(A1[1], A1[3], pr + 24 * ROWP);
            const uint32_t vk = vrow + ks * 32;
#pragma unroll
            for (int ct = 0; ct < 16; ct++) {
                uint32_t b0, b1;
                lds64(b0, b1, vk + ct * 8 * ROWV);
                mma_h16(acc[0][ct], A0, b0, b1);
                mma_h16(acc[1][ct], A1, b0, b1);
            }
        }
    }

    // ---- combine row sums across the two key-halves ----
    __syncthreads();
#pragma unroll
    for (int qt = 0; qt < 2; qt++) {
        float r0 = rs[qt][0], r1 = rs[qt][1];
        r0 += __shfl_xor_sync(0xffffffffu, r0, 1); r0 += __shfl_xor_sync(0xffffffffu, r0, 2);
        r1 += __shfl_xor_sync(0xffffffffu, r1, 1); r1 += __shfl_xor_sync(0xffffffffu, r1, 2);
        if (t4 == 0) {
            rsm[half * 128 + qbase + qt * 16 + r4]     = r0;
            rsm[half * 128 + qbase + qt * 16 + r4 + 8] = r1;
        }
    }
    __syncthreads();

    // ---- epilogue ----
    const float gm = *gamma_p;
    const float* xb = x + (size_t)b * CIN * HW_;
    float* ob = out + (size_t)b * CIN * HW_;
#pragma unroll
    for (int qt = 0; qt < 2; qt++) {
        int qa = qbase + qt * 16 + r4, qb2 = qa + 8;
        float inva = gm / (rsm[qa] + rsm[128 + qa]);
        float invb = gm / (rsm[qb2] + rsm[128 + qb2]);
        int na = n0 + qa, nb = n0 + qb2;
#pragma unroll
        for (int ct = 0; ct < 16; ct++) {
            int ch0 = half * 128 + ct * 8 + 2 * t4, ch1 = ch0 + 1;
            ob[(size_t)ch0 * HW_ + na] = fmaf(inva, acc[qt][ct][0], xb[(size_t)ch0 * HW_ + na]);
            ob[(size_t)ch1 * HW_ + na] = fmaf(inva, acc[qt][ct][1], xb[(size_t)ch1 * HW_ + na]);
            ob[(size_t)ch0 * HW_ + nb] = fmaf(invb, acc[qt][ct][2], xb[(size_t)ch0 * HW_ + nb]);
            ob[(size_t)ch1 * HW_ + nb] = fmaf(invb, acc[qt][ct][3], xb[(size_t)ch1 * HW_ + nb]);
        }
    }
}

// ---------------- launch ----------------
extern "C" void kernel_launch(void* const* d_in, const int* in_sizes, int n_in,
                              void* d_out, int out_size) {
    const float* x  = (const float*)d_in[0];
    const float* Wf = (const float*)d_in[1];
    const float* bf = (const float*)d_in[2];
    const float* Wg = (const float*)d_in[3];
    const float* bg = (const float*)d_in[4];
    const float* Wh = (const float*)d_in[5];
    const float* bh = (const float*)d_in[6];
    const float* gamma = (const float*)d_in[7];
    float* out = (float*)d_out;

    prep_kernel<<<(CIN * CIN + 255) / 256, 256>>>(Wf, bf, Wg, bg, Wh, bh);
    proj_kernel<<<dim3(HW_ / 128, NO_ / 32, B_), 256>>>(x);

    cudaFuncSetAttribute(attn_kernel, cudaFuncAttributeMaxDynamicSharedMemorySize, SMEM_BYTES);
    attn_kernel<<<dim3(HW_ / 128, B_), 256, SMEM_BYTES>>>(x, gamma, out);
}

// round 7
// speedup vs baseline: 10.6290x; 1.1300x over previous
#include <cuda_runtime.h>
#include <cuda_bf16.h>
#include <cuda_fp16.h>
#include <cstdint>

#define B_   8
#define CIN  256
#define HW_  4096
#define DQK  16
#define NO_  288
#define L2E  1.4426950408889634f
#define PSHIFT 10.0f

typedef unsigned long long u64;

// ---------------- portable PTX helpers ----------------
#define FMA2(d, a, b, c) asm("fma.rn.f32x2 %0, %1, %2, %3;" : "=l"(d) : "l"(a), "l"(b), "l"(c))
#define PACK2(d, lo, hi) asm("mov.b64 %0, {%1, %2};"        : "=l"(d) : "r"(lo), "r"(hi))
#define UNPACK2(lo, hi, s) asm("mov.b64 {%0, %1}, %2;"      : "=r"(lo), "=r"(hi) : "l"(s))

__device__ __forceinline__ uint32_t smem_u32(const void* p) {
    uint32_t a;
    asm("{ .reg .u64 t; cvta.to.shared.u64 t, %1; cvt.u32.u64 %0, t; }" : "=r"(a) : "l"(p));
    return a;
}
__device__ __forceinline__ float ex2(float v) {
    float r; asm("ex2.approx.f32 %0, %1;" : "=f"(r) : "f"(v)); return r;
}
__device__ __forceinline__ uint32_t pack_h2(float lo, float hi) {
    uint32_t d; asm("cvt.rn.f16x2.f32 %0, %1, %2;" : "=r"(d) : "f"(hi), "f"(lo)); return d;
}
__device__ __forceinline__ uint32_t pack_b2(float lo, float hi) {
    uint32_t d; asm("cvt.rn.bf16x2.f32 %0, %1, %2;" : "=r"(d) : "f"(hi), "f"(lo)); return d;
}
__device__ __forceinline__ float bfv(float v) {   // value of bf16-rounded v
    __nv_bfloat16 h = __float2bfloat16(v);
    return __bfloat162float(h);
}
__device__ __forceinline__ uint32_t lds32(uint32_t a) {
    uint32_t v; asm volatile("ld.shared.b32 %0, [%1];" : "=r"(v) : "r"(a)); return v;
}
__device__ __forceinline__ void lds64(uint32_t& x, uint32_t& y, uint32_t a) {
    asm volatile("ld.shared.v2.b32 {%0, %1}, [%2];" : "=r"(x), "=r"(y) : "r"(a));
}
__device__ __forceinline__ void sts32(uint32_t a, uint32_t v) {
    asm volatile("st.shared.b32 [%0], %1;" :: "r"(a), "r"(v));
}
#define CP16(dst, src) asm volatile("cp.async.cg.shared.global [%0], [%1], 16;" :: "r"(dst), "l"(src))
#define CP_COMMIT()    asm volatile("cp.async.commit_group;" ::: "memory")
#define CP_WAIT0()     asm volatile("cp.async.wait_group 0;" ::: "memory")
#define CP_WAIT1()     asm volatile("cp.async.wait_group 1;" ::: "memory")

// bf16 m16n8k16 (fp32 accum)
__device__ __forceinline__ void mma_ba(float* d, const uint32_t* a, uint32_t b0, uint32_t b1) {
    asm volatile("mma.sync.aligned.m16n8k16.row.col.f32.bf16.bf16.f32 "
        "{%0,%1,%2,%3}, {%4,%5,%6,%7}, {%8,%9}, {%0,%1,%2,%3};"
        : "+f"(d[0]), "+f"(d[1]), "+f"(d[2]), "+f"(d[3])
        : "r"(a[0]), "r"(a[1]), "r"(a[2]), "r"(a[3]), "r"(b0), "r"(b1));
}
__device__ __forceinline__ void mma_bz(float* d, const uint32_t* a, uint32_t b0, uint32_t b1) {
    float z = 0.f;
    asm volatile("mma.sync.aligned.m16n8k16.row.col.f32.bf16.bf16.f32 "
        "{%0,%1,%2,%3}, {%4,%5,%6,%7}, {%8,%9}, {%10,%10,%10,%10};"
        : "=f"(d[0]), "=f"(d[1]), "=f"(d[2]), "=f"(d[3])
        : "r"(a[0]), "r"(a[1]), "r"(a[2]), "r"(a[3]), "r"(b0), "r"(b1), "f"(z));
}
// fp16 m16n8k16 (fp32 accum)
__device__ __forceinline__ void mma_h16(float* d, const uint32_t* a, uint32_t b0, uint32_t b1) {
    asm volatile("mma.sync.aligned.m16n8k16.row.col.f32.f16.f16.f32 "
        "{%0,%1,%2,%3}, {%4,%5,%6,%7}, {%8,%9}, {%0,%1,%2,%3};"
        : "+f"(d[0]), "+f"(d[1]), "+f"(d[2]), "+f"(d[3])
        : "r"(a[0]), "r"(a[1]), "r"(a[2]), "r"(a[3]), "r"(b0), "r"(b1));
}

// key permutation within 16-groups for fp16 frag-contiguous V loads
__device__ __forceinline__ int kperm(int e) {
    return (((e & 7) >> 1) << 2) | (e & 1) | ((e >> 3) << 1);
}

// ---------------- scratch ----------------
__device__ float         d_gbuf[B_ * DQK * HW_];
__device__ __nv_bfloat16 d_fkm[(size_t)B_ * HW_ * 32];  // F key-major: per key 16 hi + 16 lo bf16
__device__ __half        d_hh[(size_t)B_ * CIN * HW_];  // V fp16, key-permuted within 16-groups
__device__ float         d_Wall[NO_ * CIN];
__device__ float         d_ball[NO_];

// ---------------- prep ----------------
__global__ void prep_kernel(const float* __restrict__ Wf, const float* __restrict__ bf,
                            const float* __restrict__ Wg, const float* __restrict__ bg,
                            const float* __restrict__ Wh, const float* __restrict__ bh) {
    int i = blockIdx.x * blockDim.x + threadIdx.x;
    if (i < DQK * CIN) { d_Wall[i] = Wf[i]; d_Wall[DQK * CIN + i] = Wg[i]; }
    if (i < CIN * CIN) d_Wall[2 * DQK * CIN + i] = Wh[i];
    if (i < DQK) { d_ball[i] = bf[i]; d_ball[DQK + i] = bg[i]; }
    if (i < CIN) d_ball[2 * DQK + i] = bh[i];
}

// ---------------- projection GEMM (f32x2 inner) ----------------
__global__ __launch_bounds__(256) void proj_kernel(const float* __restrict__ x) {
    const int b  = blockIdx.z;
    const int o0 = blockIdx.y * 32;
    const int m0 = blockIdx.x * 128;

    __shared__ float Ws[32][36];
    __shared__ float Xs[32][128];

    const int tid = threadIdx.x;
    const int tr = tid >> 5, tc = tid & 31;

    u64 acc2[4][2];
#pragma unroll
    for (int i = 0; i < 4; i++) {
        uint32_t bi = __float_as_uint(d_ball[o0 + tr * 4 + i]);
        PACK2(acc2[i][0], bi, bi);
        PACK2(acc2[i][1], bi, bi);
    }

    const float* xb = x + (size_t)b * CIN * HW_;

    for (int kc = 0; kc < CIN; kc += 32) {
#pragma unroll
        for (int t = tid; t < 1024; t += 256) {
            int i = t >> 5, j = t & 31;
            Ws[j][i] = d_Wall[(o0 + i) * CIN + kc + j];
        }
#pragma unroll
        for (int t = tid; t < 4096; t += 256) {
            int j = t >> 7, mm = t & 127;
            Xs[j][mm] = xb[(size_t)(kc + j) * HW_ + m0 + mm];
        }
        __syncthreads();
#pragma unroll
        for (int kk = 0; kk < 32; kk++) {
            float4 wv = *(const float4*)&Ws[kk][tr * 4];
            ulonglong2 xv = *(const ulonglong2*)&Xs[kk][tc * 4];
            u64 w0, w1, w2, w3;
            uint32_t a0 = __float_as_uint(wv.x), a1 = __float_as_uint(wv.y);
            uint32_t a2 = __float_as_uint(wv.z), a3 = __float_as_uint(wv.w);
            PACK2(w0, a0, a0); PACK2(w1, a1, a1); PACK2(w2, a2, a2); PACK2(w3, a3, a3);
            FMA2(acc2[0][0], xv.x, w0, acc2[0][0]); FMA2(acc2[0][1], xv.y, w0, acc2[0][1]);
            FMA2(acc2[1][0], xv.x, w1, acc2[1][0]); FMA2(acc2[1][1], xv.y, w1, acc2[1][1]);
            FMA2(acc2[2][0], xv.x, w2, acc2[2][0]); FMA2(acc2[2][1], xv.y, w2, acc2[2][1]);
            FMA2(acc2[3][0], xv.x, w3, acc2[3][0]); FMA2(acc2[3][1], xv.y, w3, acc2[3][1]);
        }
        __syncthreads();
    }

#pragma unroll
    for (int i = 0; i < 4; i++) {
        int o = o0 + tr * 4 + i;
        float av[4];
        uint32_t lo, hi;
        UNPACK2(lo, hi, acc2[i][0]); av[0] = __uint_as_float(lo); av[1] = __uint_as_float(hi);
        UNPACK2(lo, hi, acc2[i][1]); av[2] = __uint_as_float(lo); av[3] = __uint_as_float(hi);
#pragma unroll
        for (int j = 0; j < 4; j++) {
            int m = m0 + tc * 4 + j;
            float v = av[j];
            if (o < DQK) {
                // F key-major bf16 hi/lo
                __nv_bfloat16 h = __float2bfloat16(v);
                float r = v - __bfloat162float(h);
                size_t base = ((size_t)b * HW_ + m) * 32;
                d_fkm[base + o] = h;
                d_fkm[base + o + 16] = __float2bfloat16(r);
            } else if (o < 2 * DQK) {
                d_gbuf[((size_t)b * DQK + (o - DQK)) * HW_ + m] = v;
            } else {
                int mp = (m & ~15) | kperm(m & 15);
                d_hh[((size_t)b * CIN + (o - 2 * DQK)) * HW_ + mp] = __float2half_rn(v);
            }
        }
    }
}

// ---------------- attention: bf16x3 QK (+bf16 prepass) + fp16 PV, 1-sync pipeline ----------------
// smem: F 3 slots x (64 keys x 80B: 16 hi bf16 @0..31, 16 lo @32..63, pad)
//       V 3 slots x (256 ch x 160B)
//       P 2 slots x (128 q x 160B)
//       RS 256 floats
#define FROW 80
#define FSZ  5120
#define VROW 160
#define VSZ  40960
#define PROW 160
#define PSZ  20480
#define OFF_F 0
#define OFF_V 15360
#define OFF_P 138240
#define OFF_RS 179200
#define SMEM_BYTES 180224

__device__ __forceinline__ void load_tile(uint32_t sb, int slot,
                                          const __nv_bfloat16* fkm, const __half* vb,
                                          int m0, int tid) {
    uint32_t fdst = sb + OFF_F + slot * FSZ;
    {
        int key = tid >> 2, g = tid & 3;
        CP16(fdst + key * FROW + g * 16, fkm + (size_t)(m0 + key) * 32 + g * 8);
    }
    uint32_t vdst = sb + OFF_V + slot * VSZ;
#pragma unroll
    for (int j = 0; j < 8; j++) {
        int i = tid + 256 * j;
        int row = i >> 3, c = i & 7;
        CP16(vdst + row * VROW + c * 16, vb + (size_t)row * HW_ + m0 + c * 8);
    }
    CP_COMMIT();
}

__device__ __forceinline__ void load_f(uint32_t sb, int slot,
                                       const __nv_bfloat16* fkm, int m0, int tid) {
    if (tid < 128) {
        int key = tid >> 1, g = tid & 1;   // hi plane only (bytes 0..31)
        CP16(sb + OFF_F + slot * FSZ + key * FROW + g * 16, fkm + (size_t)(m0 + key) * 32 + g * 8);
    }
    CP_COMMIT();
}

// QK (bf16 x3) + softmax + P store for one tile
__device__ __forceinline__ void qk_tile(uint32_t sb, int fslot, int pslot,
                                        const uint32_t qh[2][4], const uint32_t ql[2][4],
                                        const float negml[2][2], float rs[2][2],
                                        int half, int t4, int r4, int qbase) {
    const uint32_t fb_ = sb + OFF_F + fslot * FSZ + (half * 32 + r4) * FROW + t4 * 4;
    float s[2][4][4];
#pragma unroll
    for (int nt = 0; nt < 4; nt++) {
        uint32_t ar = fb_ + nt * 8 * FROW;
        uint32_t bh0 = lds32(ar), bh1 = lds32(ar + 16);
        uint32_t bl0 = lds32(ar + 32), bl1 = lds32(ar + 48);
        mma_bz(s[0][nt], qh[0], bh0, bh1);
        mma_bz(s[1][nt], qh[1], bh0, bh1);
        mma_ba(s[0][nt], ql[0], bh0, bh1);
        mma_ba(s[1][nt], ql[1], bh0, bh1);
        mma_ba(s[0][nt], qh[0], bl0, bl1);
        mma_ba(s[1][nt], qh[1], bl0, bl1);
    }
    const uint32_t pbase = sb + OFF_P + pslot * PSZ + qbase * PROW;
    const uint32_t poff = half * 64 + t4 * 8;
#pragma unroll
    for (int qt = 0; qt < 2; qt++) {
        uint32_t prow = pbase + (qt * 16 + r4) * PROW;
#pragma unroll
        for (int nt = 0; nt < 4; nt++) {
            float pa0 = ex2(fmaf(s[qt][nt][0], L2E, negml[qt][0]));
            float pa1 = ex2(fmaf(s[qt][nt][1], L2E, negml[qt][0]));
            float pb0 = ex2(fmaf(s[qt][nt][2], L2E, negml[qt][1]));
            float pb1 = ex2(fmaf(s[qt][nt][3], L2E, negml[qt][1]));
            rs[qt][0] += pa0 + pa1;
            rs[qt][1] += pb0 + pb1;
            uint32_t off = poff + (nt >> 1) * 32 + (nt & 1) * 4;
            sts32(prow + off, pack_h2(pa0, pa1));
            sts32(prow + 8 * PROW + off, pack_h2(pb0, pb1));
        }
    }
}

__device__ __forceinline__ void pv_tile(uint32_t sb, int vslot, int pslot,
                                        float acc0[16][4], float acc1[16][4],
                                        int half, int t4, int r4, int qbase) {
    const uint32_t pbase = sb + OFF_P + pslot * PSZ + qbase * PROW;
    const uint32_t vrow = sb + OFF_V + vslot * VSZ + (half * 128 + r4) * VROW + t4 * 8;
#pragma unroll
    for (int ks = 0; ks < 4; ks++) {
        uint32_t A0[4], A1[4];
        uint32_t pr = pbase + r4 * PROW + ks * 32 + t4 * 8;
        lds64(A0[0], A0[2], pr);
        lds64(A0[1], A0[3], pr + 8 * PROW);
        lds64(A1[0], A1[2], pr + 16 * PROW);
        lds64(A1[1], A1[3], pr + 24 * PROW);
        const uint32_t vk = vrow + ks * 32;
#pragma unroll
        for (int ct = 0; ct < 16; ct++) {
            uint32_t b0, b1;
            lds64(b0, b1, vk + ct * 8 * VROW);
            mma_h16(acc0[ct], A0, b0, b1);
            mma_h16(acc1[ct], A1, b0, b1);
        }
    }
}

__global__ __launch_bounds__(256, 1) void attn_kernel(const float* __restrict__ x,
                                                      const float* __restrict__ gamma_p,
                                                      float* __restrict__ out) {
    extern __shared__ char smraw[];
    const uint32_t sb = smem_u32(smraw);
    float* rsm = (float*)(smraw + OFF_RS);
    const int tid = threadIdx.x, wid = tid >> 5, lane = tid & 31;
    const int t4 = lane & 3, r4 = lane >> 2;
    const int qg = wid >> 1, half = wid & 1;
    const int qbase = qg * 32;
    const int b = blockIdx.y, n0 = blockIdx.x * 128;

    const float*         gb  = d_gbuf + (size_t)b * DQK * HW_;
    const __nv_bfloat16* fkm = d_fkm + (size_t)b * HW_ * 32;
    const __half*        vbp = d_hh  + (size_t)b * CIN * HW_;

    // ---- Q fragments: bf16 hi/lo ----
    uint32_t qh[2][4], ql[2][4];
#pragma unroll
    for (int qt = 0; qt < 2; qt++) {
        const int nq = n0 + qbase + qt * 16 + r4;
#pragma unroll
        for (int h = 0; h < 2; h++) {
            int k0 = 2 * t4 + 8 * h;
            float va0 = gb[(size_t)k0 * HW_ + nq];
            float va1 = gb[(size_t)(k0 + 1) * HW_ + nq];
            float vb0 = gb[(size_t)k0 * HW_ + nq + 8];
            float vb1 = gb[(size_t)(k0 + 1) * HW_ + nq + 8];
            float ha0 = bfv(va0), ha1 = bfv(va1), hb0 = bfv(vb0), hb1 = bfv(vb1);
            qh[qt][2 * h]     = pack_b2(ha0, ha1);
            qh[qt][2 * h + 1] = pack_b2(hb0, hb1);
            ql[qt][2 * h]     = pack_b2(va0 - ha0, va1 - ha1);
            ql[qt][2 * h + 1] = pack_b2(vb0 - hb0, vb1 - hb1);
        }
    }

    // ================= PREPASS: per-row max (bf16 hi, single product) =================
    float smax[2][2] = {{-1e30f, -1e30f}, {-1e30f, -1e30f}};
    load_f(sb, 0, fkm, 0, tid);
    load_f(sb, 1, fkm, 64, tid);
    for (int i = 0; i < 64; i++) {
        CP_WAIT0();
        __syncthreads();
        if (i + 2 < 64) load_f(sb, (i + 2) % 3, fkm, (i + 2) * 64, tid);
        const uint32_t fb_ = sb + OFF_F + (i % 3) * FSZ + (half * 32 + r4) * FROW + t4 * 4;
#pragma unroll
        for (int nt = 0; nt < 4; nt++) {
            uint32_t ar = fb_ + nt * 8 * FROW;
            uint32_t b0 = lds32(ar), b1 = lds32(ar + 16);
            float s0[4], s1[4];
            mma_bz(s0, qh[0], b0, b1);
            mma_bz(s1, qh[1], b0, b1);
            smax[0][0] = fmaxf(smax[0][0], fmaxf(s0[0], s0[1]));
            smax[0][1] = fmaxf(smax[0][1], fmaxf(s0[2], s0[3]));
            smax[1][0] = fmaxf(smax[1][0], fmaxf(s1[0], s1[1]));
            smax[1][1] = fmaxf(smax[1][1], fmaxf(s1[2], s1[3]));
        }
    }
#pragma unroll
    for (int qt = 0; qt < 2; qt++)
#pragma unroll
        for (int j = 0; j < 2; j++) {
            float m = smax[qt][j];
            m = fmaxf(m, __shfl_xor_sync(0xffffffffu, m, 1));
            m = fmaxf(m, __shfl_xor_sync(0xffffffffu, m, 2));
            smax[qt][j] = m;
        }
    __syncthreads();
    if (t4 == 0) {
#pragma unroll
        for (int qt = 0; qt < 2; qt++) {
            rsm[half * 128 + qbase + qt * 16 + r4]     = smax[qt][0];
            rsm[half * 128 + qbase + qt * 16 + r4 + 8] = smax[qt][1];
        }
    }
    __syncthreads();
    float negml[2][2];
#pragma unroll
    for (int qt = 0; qt < 2; qt++) {
        int row = qbase + qt * 16 + r4;
        negml[qt][0] = PSHIFT - fmaxf(rsm[row], rsm[128 + row]) * L2E;
        negml[qt][1] = PSHIFT - fmaxf(rsm[row + 8], rsm[128 + row + 8]) * L2E;
    }

    // ================= MAIN LOOP (1 sync/tile) =================
    float acc0[16][4], acc1[16][4];
#pragma unroll
    for (int ct = 0; ct < 16; ct++) {
        acc0[ct][0] = acc0[ct][1] = acc0[ct][2] = acc0[ct][3] = 0.f;
        acc1[ct][0] = acc1[ct][1] = acc1[ct][2] = acc1[ct][3] = 0.f;
    }
    float rs[2][2] = {{0.f, 0.f}, {0.f, 0.f}};

    load_tile(sb, 0, fkm, vbp, 0, tid);
    load_tile(sb, 1, fkm, vbp, 64, tid);
    CP_WAIT1();
    __syncthreads();
    qk_tile(sb, 0, 0, qh, ql, negml, rs, half, t4, r4, qbase);   // P(0)

    for (int i = 0; i < 64; i++) {
        CP_WAIT0();
        __syncthreads();   // P(i) visible; V(i) & F(i+1) loaded; stale buffers free
        if (i + 2 < 64) load_tile(sb, (i + 2) % 3, fkm, vbp, (i + 2) * 64, tid);
        if (i + 1 < 64) qk_tile(sb, (i + 1) % 3, (i + 1) & 1, qh, ql, negml, rs, half, t4, r4, qbase);
        pv_tile(sb, i % 3, i & 1, acc0, acc1, half, t4, r4, qbase);
    }

    // ---- combine row sums across key-halves ----
    __syncthreads();
#pragma unroll
    for (int qt = 0; qt < 2; qt++) {
        float r0 = rs[qt][0], r1 = rs[qt][1];
        r0 += __shfl_xor_sync(0xffffffffu, r0, 1); r0 += __shfl_xor_sync(0xffffffffu, r0, 2);
        r1 += __shfl_xor_sync(0xffffffffu, r1, 1); r1 += __shfl_xor_sync(0xffffffffu, r1, 2);
        if (t4 == 0) {
            rsm[half * 128 + qbase + qt * 16 + r4]     = r0;
            rsm[half * 128 + qbase + qt * 16 + r4 + 8] = r1;
        }
    }
    __syncthreads();

    // ---- epilogue ----
    const float gm = *gamma_p;
    const float* xb = x + (size_t)b * CIN * HW_;
    float* ob = out + (size_t)b * CIN * HW_;
#pragma unroll
    for (int qt = 0; qt < 2; qt++) {
        float (*acc)[4] = qt ? acc1 : acc0;
        int qa = qbase + qt * 16 + r4, qb2 = qa + 8;
        float inva = gm / (rsm[qa] + rsm[128 + qa]);
        float invb = gm / (rsm[qb2] + rsm[128 + qb2]);
        int na = n0 + qa, nb = n0 + qb2;
#pragma unroll
        for (int ct = 0; ct < 16; ct++) {
            int ch0 = half * 128 + ct * 8 + 2 * t4, ch1 = ch0 + 1;
            ob[(size_t)ch0 * HW_ + na] = fmaf(inva, acc[ct][0], xb[(size_t)ch0 * HW_ + na]);
            ob[(size_t)ch1 * HW_ + na] = fmaf(inva, acc[ct][1], xb[(size_t)ch1 * HW_ + na]);
            ob[(size_t)ch0 * HW_ + nb] = fmaf(invb, acc[ct][2], xb[(size_t)ch0 * HW_ + nb]);
            ob[(size_t)ch1 * HW_ + nb] = fmaf(invb, acc[ct][3], xb[(size_t)ch1 * HW_ + nb]);
        }
    }
}

// ---------------- launch ----------------
extern "C" void kernel_launch(void* const* d_in, const int* in_sizes, int n_in,
                              void* d_out, int out_size) {
    const float* x  = (const float*)d_in[0];
    const float* Wf = (const float*)d_in[1];
    const float* bf = (const float*)d_in[2];
    const float* Wg = (const float*)d_in[3];
    const float* bg = (const float*)d_in[4];
    const float* Wh = (const float*)d_in[5];
    const float* bh = (const float*)d_in[6];
    const float* gamma = (const float*)d_in[7];
    float* out = (float*)d_out;

    prep_kernel<<<(CIN * CIN + 255) / 256, 256>>>(Wf, bf, Wg, bg, Wh, bh);
    proj_kernel<<<dim3(HW_ / 128, NO_ / 32, B_), 256>>>(x);

    cudaFuncSetAttribute(attn_kernel, cudaFuncAttributeMaxDynamicSharedMemorySize, SMEM_BYTES);
    attn_kernel<<<dim3(HW_ / 128, B_), 256, SMEM_BYTES>>>(x, gamma, out);
}

// round 9
// speedup vs baseline: 12.3928x; 1.1659x over previous
#include <cuda_runtime.h>
#include <cuda_bf16.h>
#include <cuda_fp16.h>
#include <cstdint>

#define B_   8
#define CIN  256
#define HW_  4096
#define DQK  16
#define NO_  288
#define L2E  1.4426950408889634f
#define PSHIFT 10.0f

typedef unsigned long long u64;

// ---------------- portable PTX helpers ----------------
__device__ __forceinline__ uint32_t smem_u32(const void* p) {
    uint32_t a;
    asm("{ .reg .u64 t; cvta.to.shared.u64 t, %1; cvt.u32.u64 %0, t; }" : "=r"(a) : "l"(p));
    return a;
}
__device__ __forceinline__ float ex2(float v) {
    float r; asm("ex2.approx.f32 %0, %1;" : "=f"(r) : "f"(v)); return r;
}
__device__ __forceinline__ uint32_t pack_h2(float lo, float hi) {
    uint32_t d; asm("cvt.rn.f16x2.f32 %0, %1, %2;" : "=r"(d) : "f"(hi), "f"(lo)); return d;
}
__device__ __forceinline__ uint32_t pack_b2(float lo, float hi) {
    uint32_t d; asm("cvt.rn.bf16x2.f32 %0, %1, %2;" : "=r"(d) : "f"(hi), "f"(lo)); return d;
}
__device__ __forceinline__ float bfv(float v) {
    __nv_bfloat16 h = __float2bfloat16(v);
    return __bfloat162float(h);
}
__device__ __forceinline__ uint32_t lds32(uint32_t a) {
    uint32_t v; asm volatile("ld.shared.b32 %0, [%1];" : "=r"(v) : "r"(a)); return v;
}
__device__ __forceinline__ void lds64(uint32_t& x, uint32_t& y, uint32_t a) {
    asm volatile("ld.shared.v2.b32 {%0, %1}, [%2];" : "=r"(x), "=r"(y) : "r"(a));
}
__device__ __forceinline__ void sts32(uint32_t a, uint32_t v) {
    asm volatile("st.shared.b32 [%0], %1;" :: "r"(a), "r"(v));
}
#define CP16(dst, src) asm volatile("cp.async.cg.shared.global [%0], [%1], 16;" :: "r"(dst), "l"(src))
#define CP_COMMIT()    asm volatile("cp.async.commit_group;" ::: "memory")
#define CP_WAIT0()     asm volatile("cp.async.wait_group 0;" ::: "memory")
#define CP_WAIT1()     asm volatile("cp.async.wait_group 1;" ::: "memory")

// bf16 m16n8k16 (fp32 accum)
__device__ __forceinline__ void mma_ba(float* d, const uint32_t* a, uint32_t b0, uint32_t b1) {
    asm volatile("mma.sync.aligned.m16n8k16.row.col.f32.bf16.bf16.f32 "
        "{%0,%1,%2,%3}, {%4,%5,%6,%7}, {%8,%9}, {%0,%1,%2,%3};"
        : "+f"(d[0]), "+f"(d[1]), "+f"(d[2]), "+f"(d[3])
        : "r"(a[0]), "r"(a[1]), "r"(a[2]), "r"(a[3]), "r"(b0), "r"(b1));
}
__device__ __forceinline__ void mma_bz(float* d, const uint32_t* a, uint32_t b0, uint32_t b1) {
    float z = 0.f;
    asm volatile("mma.sync.aligned.m16n8k16.row.col.f32.bf16.bf16.f32 "
        "{%0,%1,%2,%3}, {%4,%5,%6,%7}, {%8,%9}, {%10,%10,%10,%10};"
        : "=f"(d[0]), "=f"(d[1]), "=f"(d[2]), "=f"(d[3])
        : "r"(a[0]), "r"(a[1]), "r"(a[2]), "r"(a[3]), "r"(b0), "r"(b1), "f"(z));
}
// fp16 m16n8k16 (fp32 accum)
__device__ __forceinline__ void mma_h16(float* d, const uint32_t* a, uint32_t b0, uint32_t b1) {
    asm volatile("mma.sync.aligned.m16n8k16.row.col.f32.f16.f16.f32 "
        "{%0,%1,%2,%3}, {%4,%5,%6,%7}, {%8,%9}, {%0,%1,%2,%3};"
        : "+f"(d[0]), "+f"(d[1]), "+f"(d[2]), "+f"(d[3])
        : "r"(a[0]), "r"(a[1]), "r"(a[2]), "r"(a[3]), "r"(b0), "r"(b1));
}

// key permutation within 16-groups (pairs stay adjacent: kperm(2j+1)=kperm(2j)+1)
__device__ __forceinline__ int kperm(int e) {
    return (((e & 7) >> 1) << 2) | (e & 1) | ((e >> 3) << 1);
}

// ---------------- scratch ----------------
__device__ float         d_gbuf[B_ * DQK * HW_];
__device__ __nv_bfloat16 d_fkm[(size_t)B_ * HW_ * 32];   // F key-major: 16 hi + 16 lo bf16
__device__ __half        d_hh[(size_t)B_ * CIN * HW_];   // V fp16, key-permuted within 16-groups
__device__ __nv_bfloat16 d_xt[(size_t)B_ * HW_ * 512];   // x pixel-major: [b][px][plane][c]
__device__ __nv_bfloat16 d_wt[NO_ * 512];                // W: [o][plane][c]
__device__ float         d_ball[NO_];

// ---------------- prep: W -> bf16 hi/lo + bias ----------------
__global__ void prep_kernel(const float* __restrict__ Wf, const float* __restrict__ bf,
                            const float* __restrict__ Wg, const float* __restrict__ bg,
                            const float* __restrict__ Wh, const float* __restrict__ bh) {
    int i = blockIdx.x * blockDim.x + threadIdx.x;
    if (i >= NO_ * CIN) return;
    int o = i >> 8, c = i & 255;
    float w = (o < 16) ? Wf[o * 256 + c] : ((o < 32) ? Wg[(o - 16) * 256 + c] : Wh[(o - 32) * 256 + c]);
    float h = bfv(w);
    d_wt[o * 512 + c]       = __float2bfloat16(h);
    d_wt[o * 512 + 256 + c] = __float2bfloat16(w - h);
    if (c == 0) d_ball[o] = (o < 16) ? bf[o] : ((o < 32) ? bg[o - 16] : bh[o - 32]);
}

// ---------------- xconv: x fp32 [b][c][px] -> bf16 hi/lo [b][px][plane][c] ----------------
__global__ __launch_bounds__(256) void xconv_kernel(const float* __restrict__ x) {
    __shared__ float tx[32][65];
    const int px0 = blockIdx.x * 64;
    const int c0  = blockIdx.y * 32;
    const int b   = blockIdx.z;
    const int tid = threadIdx.x;
    const float* xb = x + (size_t)b * CIN * HW_;
#pragma unroll
    for (int it = 0; it < 8; it++) {
        int e = tid + 256 * it;
        int c = e >> 6, p = e & 63;
        tx[c][p] = xb[(size_t)(c0 + c) * HW_ + px0 + p];
    }
    __syncthreads();
    uint32_t* dst = (uint32_t*)d_xt;
#pragma unroll
    for (int it = 0; it < 8; it++) {
        int e = tid + 256 * it;
        int px = e >> 5, q = e & 31;
        int plane = q >> 4, cp = q & 15;
        float v0 = tx[2 * cp][px], v1 = tx[2 * cp + 1][px];
        float h0 = bfv(v0), h1 = bfv(v1);
        uint32_t outw = plane ? pack_b2(v0 - h0, v1 - h1) : pack_b2(h0, h1);
        size_t idx = (((size_t)b * HW_ + px0 + px) * 512 + plane * 256 + c0 + 2 * cp) >> 1;
        dst[idx] = outw;
    }
}

// ---------------- proj GEMM on tensor cores (bf16 x3) ----------------
// CTA: 288 o x 128 px. 8 warps = 2 o-halves (144 o = 9 m-tiles) x 4 px-quarters (32 px = 4 n-tiles).
// smem: X 2 slots x (128 px x 144B), W 2 slots x (288 o x 144B) — both strides 16B-multiple for cp.async
#define PX_STRIDE 144
#define PW_STRIDE 144
#define PX_SZ     (128 * PX_STRIDE)
#define PW_OFF    (2 * PX_SZ)
#define PW_SZ     (288 * PW_STRIDE)
#define PROJ_SMEM (PW_OFF + 2 * PW_SZ)

__device__ __forceinline__ void proj_load(uint32_t sb, int slot, int b, int px0, int kc, int tid) {
    uint32_t xdst = sb + slot * PX_SZ;
    const __nv_bfloat16* xsrc = d_xt + ((size_t)b * HW_ + px0) * 512 + kc;
#pragma unroll
    for (int j = 0; j < 4; j++) {
        int e = tid * 4 + j;
        int px = e >> 3, sub = e & 7;
        int pl = sub >> 2, c16 = sub & 3;
        CP16(xdst + px * PX_STRIDE + pl * 64 + c16 * 16, xsrc + (size_t)px * 512 + pl * 256 + c16 * 8);
    }
    uint32_t wdst = sb + PW_OFF + slot * PW_SZ;
    const __nv_bfloat16* wsrc = d_wt + kc;
#pragma unroll
    for (int it = 0; it < 9; it++) {
        int e = tid + 256 * it;
        int o = e >> 3, sub = e & 7;
        int pl = sub >> 2, c16 = sub & 3;
        CP16(wdst + o * PW_STRIDE + pl * 64 + c16 * 16, wsrc + (size_t)o * 512 + pl * 256 + c16 * 8);
    }
    CP_COMMIT();
}

__global__ __launch_bounds__(256, 1) void proj_mma_kernel() {
    extern __shared__ char smraw[];
    const uint32_t sb = smem_u32(smraw);
    const int tid = threadIdx.x, wid = tid >> 5, lane = tid & 31;
    const int t4 = lane & 3, r4 = lane >> 2;
    const int oh = wid & 1, pq = wid >> 1;
    const int px0 = blockIdx.x * 128;
    const int b = blockIdx.y;

    float acc[9][4][4];
#pragma unroll
    for (int mt = 0; mt < 9; mt++)
#pragma unroll
        for (int nt = 0; nt < 4; nt++) { acc[mt][nt][0] = acc[mt][nt][1] = acc[mt][nt][2] = acc[mt][nt][3] = 0.f; }

    proj_load(sb, 0, b, px0, 0, tid);

    for (int ch = 0; ch < 8; ch++) {
        CP_WAIT0();
        __syncthreads();
        if (ch + 1 < 8) proj_load(sb, (ch + 1) & 1, b, px0, (ch + 1) * 32, tid);

        const uint32_t xs = sb + (ch & 1) * PX_SZ;
        const uint32_t ws = sb + PW_OFF + (ch & 1) * PW_SZ;
#pragma unroll
        for (int ks = 0; ks < 2; ks++) {
            uint32_t bh[4][2], bl[4][2];
#pragma unroll
            for (int nt = 0; nt < 4; nt++) {
                uint32_t base = xs + (pq * 32 + nt * 8 + r4) * PX_STRIDE + ks * 32 + t4 * 4;
                bh[nt][0] = lds32(base);       bh[nt][1] = lds32(base + 16);
                bl[nt][0] = lds32(base + 64);  bl[nt][1] = lds32(base + 80);
            }
#pragma unroll
            for (int mt = 0; mt < 9; mt++) {
                uint32_t base = ws + (oh * 144 + mt * 16 + r4) * PW_STRIDE + ks * 32 + t4 * 4;
                uint32_t Ah[4], Al[4];
                Ah[0] = lds32(base);                 Ah[1] = lds32(base + 8 * PW_STRIDE);
                Ah[2] = lds32(base + 16);            Ah[3] = lds32(base + 8 * PW_STRIDE + 16);
                Al[0] = lds32(base + 64);            Al[1] = lds32(base + 8 * PW_STRIDE + 64);
                Al[2] = lds32(base + 80);            Al[3] = lds32(base + 8 * PW_STRIDE + 80);
#pragma unroll
                for (int nt = 0; nt < 4; nt++) {
                    mma_ba(acc[mt][nt], Ah, bh[nt][0], bh[nt][1]);
                    mma_ba(acc[mt][nt], Al, bh[nt][0], bh[nt][1]);
                    mma_ba(acc[mt][nt], Ah, bl[nt][0], bl[nt][1]);
                }
            }
        }
        __syncthreads();
    }

    // ---- epilogue: route to f (bf16 hi/lo), g (fp32), V (fp16 kperm) ----
#pragma unroll
    for (int mt = 0; mt < 9; mt++) {
#pragma unroll
        for (int nt = 0; nt < 4; nt++) {
            int px = pq * 32 + nt * 8 + 2 * t4;   // even
#pragma unroll
            for (int r = 0; r < 2; r++) {
                int o = oh * 144 + mt * 16 + r4 + 8 * r;
                float bias = d_ball[o];
                float va = acc[mt][nt][2 * r]     + bias;
                float vb = acc[mt][nt][2 * r + 1] + bias;
                if (oh == 0 && mt == 0) {           // f rows 0..15
                    size_t base = ((size_t)b * HW_ + px0 + px) * 32;
                    float ha = bfv(va), hb = bfv(vb);
                    d_fkm[base + o]           = __float2bfloat16(ha);
                    d_fkm[base + 16 + o]      = __float2bfloat16(va - ha);
                    d_fkm[base + 32 + o]      = __float2bfloat16(hb);
                    d_fkm[base + 48 + o]      = __float2bfloat16(vb - hb);
                } else if (oh == 0 && mt == 1) {    // g rows 16..31
                    float2 st; st.x = va; st.y = vb;
                    *(float2*)&d_gbuf[((size_t)b * DQK + (o - 16)) * HW_ + px0 + px] = st;
                } else {                            // V rows 32..287
                    int c = o - 32;
                    int pxp = (px & ~15) | kperm(px & 15);
                    *(uint32_t*)&d_hh[((size_t)b * CIN + c) * HW_ + px0 + pxp] = pack_h2(va, vb);
                }
            }
        }
    }
}

// ---------------- attention (unchanged from round 7) ----------------
#define FROW 80
#define FSZ  5120
#define VROW 160
#define VSZ  40960
#define PROW 160
#define PSZ  20480
#define OFF_F 0
#define OFF_V 15360
#define OFF_P 138240
#define OFF_RS 179200
#define SMEM_BYTES 180224

__device__ __forceinline__ void load_tile(uint32_t sb, int slot,
                                          const __nv_bfloat16* fkm, const __half* vb,
                                          int m0, int tid) {
    uint32_t fdst = sb + OFF_F + slot * FSZ;
    {
        int key = tid >> 2, g = tid & 3;
        CP16(fdst + key * FROW + g * 16, fkm + (size_t)(m0 + key) * 32 + g * 8);
    }
    uint32_t vdst = sb + OFF_V + slot * VSZ;
#pragma unroll
    for (int j = 0; j < 8; j++) {
        int i = tid + 256 * j;
        int row = i >> 3, c = i & 7;
        CP16(vdst + row * VROW + c * 16, vb + (size_t)row * HW_ + m0 + c * 8);
    }
    CP_COMMIT();
}

__device__ __forceinline__ void load_f(uint32_t sb, int slot,
                                       const __nv_bfloat16* fkm, int m0, int tid) {
    if (tid < 128) {
        int key = tid >> 1, g = tid & 1;
        CP16(sb + OFF_F + slot * FSZ + key * FROW + g * 16, fkm + (size_t)(m0 + key) * 32 + g * 8);
    }
    CP_COMMIT();
}

__device__ __forceinline__ void qk_tile(uint32_t sb, int fslot, int pslot,
                                        const uint32_t qh[2][4], const uint32_t ql[2][4],
                                        const float negml[2][2], float rs[2][2],
                                        int half, int t4, int r4, int qbase) {
    const uint32_t fb_ = sb + OFF_F + fslot * FSZ + (half * 32 + r4) * FROW + t4 * 4;
    float s[2][4][4];
#pragma unroll
    for (int nt = 0; nt < 4; nt++) {
        uint32_t ar = fb_ + nt * 8 * FROW;
        uint32_t bh0 = lds32(ar), bh1 = lds32(ar + 16);
        uint32_t bl0 = lds32(ar + 32), bl1 = lds32(ar + 48);
        mma_bz(s[0][nt], qh[0], bh0, bh1);
        mma_bz(s[1][nt], qh[1], bh0, bh1);
        mma_ba(s[0][nt], ql[0], bh0, bh1);
        mma_ba(s[1][nt], ql[1], bh0, bh1);
        mma_ba(s[0][nt], qh[0], bl0, bl1);
        mma_ba(s[1][nt], qh[1], bl0, bl1);
    }
    const uint32_t pbase = sb + OFF_P + pslot * PSZ + qbase * PROW;
    const uint32_t poff = half * 64 + t4 * 8;
#pragma unroll
    for (int qt = 0; qt < 2; qt++) {
        uint32_t prow = pbase + (qt * 16 + r4) * PROW;
#pragma unroll
        for (int nt = 0; nt < 4; nt++) {
            float pa0 = ex2(fmaf(s[qt][nt][0], L2E, negml[qt][0]));
            float pa1 = ex2(fmaf(s[qt][nt][1], L2E, negml[qt][0]));
            float pb0 = ex2(fmaf(s[qt][nt][2], L2E, negml[qt][1]));
            float pb1 = ex2(fmaf(s[qt][nt][3], L2E, negml[qt][1]));
            rs[qt][0] += pa0 + pa1;
            rs[qt][1] += pb0 + pb1;
            uint32_t off = poff + (nt >> 1) * 32 + (nt & 1) * 4;
            sts32(prow + off, pack_h2(pa0, pa1));
            sts32(prow + 8 * PROW + off, pack_h2(pb0, pb1));
        }
    }
}

__device__ __forceinline__ void pv_tile(uint32_t sb, int vslot, int pslot,
                                        float acc0[16][4], float acc1[16][4],
                                        int half, int t4, int r4, int qbase) {
    const uint32_t pbase = sb + OFF_P + pslot * PSZ + qbase * PROW;
    const uint32_t vrow = sb + OFF_V + vslot * VSZ + (half * 128 + r4) * VROW + t4 * 8;
#pragma unroll
    for (int ks = 0; ks < 4; ks++) {
        uint32_t A0[4], A1[4];
        uint32_t pr = pbase + r4 * PROW + ks * 32 + t4 * 8;
        lds64(A0[0], A0[2], pr);
        lds64(A0[1], A0[3], pr + 8 * PROW);
        lds64(A1[0], A1[2], pr + 16 * PROW);
        lds64(A1[1], A1[3], pr + 24 * PROW);
        const uint32_t vk = vrow + ks * 32;
#pragma unroll
        for (int ct = 0; ct < 16; ct++) {
            uint32_t b0, b1;
            lds64(b0, b1, vk + ct * 8 * VROW);
            mma_h16(acc0[ct], A0, b0, b1);
            mma_h16(acc1[ct], A1, b0, b1);
        }
    }
}

__global__ __launch_bounds__(256, 1) void attn_kernel(const float* __restrict__ x,
                                                      const float* __restrict__ gamma_p,
                                                      float* __restrict__ out) {
    extern __shared__ char smraw[];
    const uint32_t sb = smem_u32(smraw);
    float* rsm = (float*)(smraw + OFF_RS);
    const int tid = threadIdx.x, wid = tid >> 5, lane = tid & 31;
    const int t4 = lane & 3, r4 = lane >> 2;
    const int qg = wid >> 1, half = wid & 1;
    const int qbase = qg * 32;
    const int b = blockIdx.y, n0 = blockIdx.x * 128;

    const float*         gb  = d_gbuf + (size_t)b * DQK * HW_;
    const __nv_bfloat16* fkm = d_fkm + (size_t)b * HW_ * 32;
    const __half*        vbp = d_hh  + (size_t)b * CIN * HW_;

    uint32_t qh[2][4], ql[2][4];
#pragma unroll
    for (int qt = 0; qt < 2; qt++) {
        const int nq = n0 + qbase + qt * 16 + r4;
#pragma unroll
        for (int h = 0; h < 2; h++) {
            int k0 = 2 * t4 + 8 * h;
            float va0 = gb[(size_t)k0 * HW_ + nq];
            float va1 = gb[(size_t)(k0 + 1) * HW_ + nq];
            float vb0 = gb[(size_t)k0 * HW_ + nq + 8];
            float vb1 = gb[(size_t)(k0 + 1) * HW_ + nq + 8];
            float ha0 = bfv(va0), ha1 = bfv(va1), hb0 = bfv(vb0), hb1 = bfv(vb1);
            qh[qt][2 * h]     = pack_b2(ha0, ha1);
            qh[qt][2 * h + 1] = pack_b2(hb0, hb1);
            ql[qt][2 * h]     = pack_b2(va0 - ha0, va1 - ha1);
            ql[qt][2 * h + 1] = pack_b2(vb0 - hb0, vb1 - hb1);
        }
    }

    // prepass: exact per-row max
    float smax[2][2] = {{-1e30f, -1e30f}, {-1e30f, -1e30f}};
    load_f(sb, 0, fkm, 0, tid);
    load_f(sb, 1, fkm, 64, tid);
    for (int i = 0; i < 64; i++) {
        CP_WAIT0();
        __syncthreads();
        if (i + 2 < 64) load_f(sb, (i + 2) % 3, fkm, (i + 2) * 64, tid);
        const uint32_t fb_ = sb + OFF_F + (i % 3) * FSZ + (half * 32 + r4) * FROW + t4 * 4;
#pragma unroll
        for (int nt = 0; nt < 4; nt++) {
            uint32_t ar = fb_ + nt * 8 * FROW;
            uint32_t b0 = lds32(ar), b1 = lds32(ar + 16);
            float s0[4], s1[4];
            mma_bz(s0, qh[0], b0, b1);
            mma_bz(s1, qh[1], b0, b1);
            smax[0][0] = fmaxf(smax[0][0], fmaxf(s0[0], s0[1]));
            smax[0][1] = fmaxf(smax[0][1], fmaxf(s0[2], s0[3]));
            smax[1][0] = fmaxf(smax[1][0], fmaxf(s1[0], s1[1]));
            smax[1][1] = fmaxf(smax[1][1], fmaxf(s1[2], s1[3]));
        }
    }
#pragma unroll
    for (int qt = 0; qt < 2; qt++)
#pragma unroll
        for (int j = 0; j < 2; j++) {
            float m = smax[qt][j];
            m = fmaxf(m, __shfl_xor_sync(0xffffffffu, m, 1));
            m = fmaxf(m, __shfl_xor_sync(0xffffffffu, m, 2));
            smax[qt][j] = m;
        }
    __syncthreads();
    if (t4 == 0) {
#pragma unroll
        for (int qt = 0; qt < 2; qt++) {
            rsm[half * 128 + qbase + qt * 16 + r4]     = smax[qt][0];
            rsm[half * 128 + qbase + qt * 16 + r4 + 8] = smax[qt][1];
        }
    }
    __syncthreads();
    float negml[2][2];
#pragma unroll
    for (int qt = 0; qt < 2; qt++) {
        int row = qbase + qt * 16 + r4;
        negml[qt][0] = PSHIFT - fmaxf(rsm[row], rsm[128 + row]) * L2E;
        negml[qt][1] = PSHIFT - fmaxf(rsm[row + 8], rsm[128 + row + 8]) * L2E;
    }

    // main loop
    float acc0[16][4], acc1[16][4];
#pragma unroll
    for (int ct = 0; ct < 16; ct++) {
        acc0[ct][0] = acc0[ct][1] = acc0[ct][2] = acc0[ct][3] = 0.f;
        acc1[ct][0] = acc1[ct][1] = acc1[ct][2] = acc1[ct][3] = 0.f;
    }
    float rs[2][2] = {{0.f, 0.f}, {0.f, 0.f}};

    load_tile(sb, 0, fkm, vbp, 0, tid);
    load_tile(sb, 1, fkm, vbp, 64, tid);
    CP_WAIT1();
    __syncthreads();
    qk_tile(sb, 0, 0, qh, ql, negml, rs, half, t4, r4, qbase);

    for (int i = 0; i < 64; i++) {
        CP_WAIT0();
        __syncthreads();
        if (i + 2 < 64) load_tile(sb, (i + 2) % 3, fkm, vbp, (i + 2) * 64, tid);
        if (i + 1 < 64) qk_tile(sb, (i + 1) % 3, (i + 1) & 1, qh, ql, negml, rs, half, t4, r4, qbase);
        pv_tile(sb, i % 3, i & 1, acc0, acc1, half, t4, r4, qbase);
    }

    __syncthreads();
#pragma unroll
    for (int qt = 0; qt < 2; qt++) {
        float r0 = rs[qt][0], r1 = rs[qt][1];
        r0 += __shfl_xor_sync(0xffffffffu, r0, 1); r0 += __shfl_xor_sync(0xffffffffu, r0, 2);
        r1 += __shfl_xor_sync(0xffffffffu, r1, 1); r1 += __shfl_xor_sync(0xffffffffu, r1, 2);
        if (t4 == 0) {
            rsm[half * 128 + qbase + qt * 16 + r4]     = r0;
            rsm[half * 128 + qbase + qt * 16 + r4 + 8] = r1;
        }
    }
    __syncthreads();

    const float gm = *gamma_p;
    const float* xb = x + (size_t)b * CIN * HW_;
    float* ob = out + (size_t)b * CIN * HW_;
#pragma unroll
    for (int qt = 0; qt < 2; qt++) {
        float (*acc)[4] = qt ? acc1 : acc0;
        int qa = qbase + qt * 16 + r4, qb2 = qa + 8;
        float inva = gm / (rsm[qa] + rsm[128 + qa]);
        float invb = gm / (rsm[qb2] + rsm[128 + qb2]);
        int na = n0 + qa, nb = n0 + qb2;
#pragma unroll
        for (int ct = 0; ct < 16; ct++) {
            int ch0 = half * 128 + ct * 8 + 2 * t4, ch1 = ch0 + 1;
            ob[(size_t)ch0 * HW_ + na] = fmaf(inva, acc[ct][0], xb[(size_t)ch0 * HW_ + na]);
            ob[(size_t)ch1 * HW_ + na] = fmaf(inva, acc[ct][1], xb[(size_t)ch1 * HW_ + na]);
            ob[(size_t)ch0 * HW_ + nb] = fmaf(invb, acc[ct][2], xb[(size_t)ch0 * HW_ + nb]);
            ob[(size_t)ch1 * HW_ + nb] = fmaf(invb, acc[ct][3], xb[(size_t)ch1 * HW_ + nb]);
        }
    }
}

// ---------------- launch ----------------
extern "C" void kernel_launch(void* const* d_in, const int* in_sizes, int n_in,
                              void* d_out, int out_size) {
    const float* x  = (const float*)d_in[0];
    const float* Wf = (const float*)d_in[1];
    const float* bf = (const float*)d_in[2];
    const float* Wg = (const float*)d_in[3];
    const float* bg = (const float*)d_in[4];
    const float* Wh = (const float*)d_in[5];
    const float* bh = (const float*)d_in[6];
    const float* gamma = (const float*)d_in[7];
    float* out = (float*)d_out;

    prep_kernel<<<(NO_ * CIN + 255) / 256, 256>>>(Wf, bf, Wg, bg, Wh, bh);
    xconv_kernel<<<dim3(HW_ / 64, CIN / 32, B_), 256>>>(x);

    cudaFuncSetAttribute(proj_mma_kernel, cudaFuncAttributeMaxDynamicSharedMemorySize, PROJ_SMEM);
    proj_mma_kernel<<<dim3(HW_ / 128, B_), 256, PROJ_SMEM>>>();

    cudaFuncSetAttribute(attn_kernel, cudaFuncAttributeMaxDynamicSharedMemorySize, SMEM_BYTES);
    attn_kernel<<<dim3(HW_ / 128, B_), 256, SMEM_BYTES>>>(x, gamma, out);
}

// round 10
// speedup vs baseline: 12.5759x; 1.0148x over previous
#include <cuda_runtime.h>
#include <cuda_bf16.h>
#include <cuda_fp16.h>
#include <cstdint>

#define B_   8
#define CIN  256
#define HW_  4096
#define DQK  16
#define NO_  288
#define L2E  1.4426950408889634f
#define PSHIFT 10.0f

typedef unsigned long long u64;

// ---------------- portable PTX helpers ----------------
__device__ __forceinline__ uint32_t smem_u32(const void* p) {
    uint32_t a;
    asm("{ .reg .u64 t; cvta.to.shared.u64 t, %1; cvt.u32.u64 %0, t; }" : "=r"(a) : "l"(p));
    return a;
}
__device__ __forceinline__ float ex2(float v) {
    float r; asm("ex2.approx.f32 %0, %1;" : "=f"(r) : "f"(v)); return r;
}
__device__ __forceinline__ uint32_t pack_h2(float lo, float hi) {
    uint32_t d; asm("cvt.rn.f16x2.f32 %0, %1, %2;" : "=r"(d) : "f"(hi), "f"(lo)); return d;
}
__device__ __forceinline__ uint32_t pack_b2(float lo, float hi) {
    uint32_t d; asm("cvt.rn.bf16x2.f32 %0, %1, %2;" : "=r"(d) : "f"(hi), "f"(lo)); return d;
}
__device__ __forceinline__ float bfv(float v) {
    __nv_bfloat16 h = __float2bfloat16(v);
    return __bfloat162float(h);
}
__device__ __forceinline__ uint32_t lds32(uint32_t a) {
    uint32_t v; asm volatile("ld.shared.b32 %0, [%1];" : "=r"(v) : "r"(a)); return v;
}
__device__ __forceinline__ void lds64(uint32_t& x, uint32_t& y, uint32_t a) {
    asm volatile("ld.shared.v2.b32 {%0, %1}, [%2];" : "=r"(x), "=r"(y) : "r"(a));
}
__device__ __forceinline__ void sts32(uint32_t a, uint32_t v) {
    asm volatile("st.shared.b32 [%0], %1;" :: "r"(a), "r"(v));
}
#define CP16(dst, src) asm volatile("cp.async.cg.shared.global [%0], [%1], 16;" :: "r"(dst), "l"(src))
#define CP_COMMIT()    asm volatile("cp.async.commit_group;" ::: "memory")
#define CP_WAIT0()     asm volatile("cp.async.wait_group 0;" ::: "memory")
#define CP_WAIT1()     asm volatile("cp.async.wait_group 1;" ::: "memory")

// bf16 m16n8k16 (fp32 accum)
__device__ __forceinline__ void mma_ba(float* d, const uint32_t* a, uint32_t b0, uint32_t b1) {
    asm volatile("mma.sync.aligned.m16n8k16.row.col.f32.bf16.bf16.f32 "
        "{%0,%1,%2,%3}, {%4,%5,%6,%7}, {%8,%9}, {%0,%1,%2,%3};"
        : "+f"(d[0]), "+f"(d[1]), "+f"(d[2]), "+f"(d[3])
        : "r"(a[0]), "r"(a[1]), "r"(a[2]), "r"(a[3]), "r"(b0), "r"(b1));
}
__device__ __forceinline__ void mma_bz(float* d, const uint32_t* a, uint32_t b0, uint32_t b1) {
    float z = 0.f;
    asm volatile("mma.sync.aligned.m16n8k16.row.col.f32.bf16.bf16.f32 "
        "{%0,%1,%2,%3}, {%4,%5,%6,%7}, {%8,%9}, {%10,%10,%10,%10};"
        : "=f"(d[0]), "=f"(d[1]), "=f"(d[2]), "=f"(d[3])
        : "r"(a[0]), "r"(a[1]), "r"(a[2]), "r"(a[3]), "r"(b0), "r"(b1), "f"(z));
}
// fp16 m16n8k16 (fp32 accum)
__device__ __forceinline__ void mma_h16(float* d, const uint32_t* a, uint32_t b0, uint32_t b1) {
    asm volatile("mma.sync.aligned.m16n8k16.row.col.f32.f16.f16.f32 "
        "{%0,%1,%2,%3}, {%4,%5,%6,%7}, {%8,%9}, {%0,%1,%2,%3};"
        : "+f"(d[0]), "+f"(d[1]), "+f"(d[2]), "+f"(d[3])
        : "r"(a[0]), "r"(a[1]), "r"(a[2]), "r"(a[3]), "r"(b0), "r"(b1));
}

// key permutation within 16-groups (pairs stay adjacent)
__device__ __forceinline__ int kperm(int e) {
    return (((e & 7) >> 1) << 2) | (e & 1) | ((e >> 3) << 1);
}

// ---------------- scratch ----------------
__device__ float         d_gbuf[B_ * DQK * HW_];
__device__ __nv_bfloat16 d_fkm[(size_t)B_ * HW_ * 32];   // F key-major: 16 hi + 16 lo bf16
__device__ __half        d_hh[(size_t)B_ * CIN * HW_];   // V fp16, key-permuted within 16-groups
__device__ __nv_bfloat16 d_xt[(size_t)B_ * HW_ * 512];   // x pixel-major: [b][px][plane][c]
__device__ __nv_bfloat16 d_wt[NO_ * 512];                // W: [o][plane][c]
__device__ float         d_ball[NO_];

// ---------------- prep: W -> bf16 hi/lo + bias ----------------
__global__ void prep_kernel(const float* __restrict__ Wf, const float* __restrict__ bf,
                            const float* __restrict__ Wg, const float* __restrict__ bg,
                            const float* __restrict__ Wh, const float* __restrict__ bh) {
    int i = blockIdx.x * blockDim.x + threadIdx.x;
    if (i >= NO_ * CIN) return;
    int o = i >> 8, c = i & 255;
    float w = (o < 16) ? Wf[o * 256 + c] : ((o < 32) ? Wg[(o - 16) * 256 + c] : Wh[(o - 32) * 256 + c]);
    float h = bfv(w);
    d_wt[o * 512 + c]       = __float2bfloat16(h);
    d_wt[o * 512 + 256 + c] = __float2bfloat16(w - h);
    if (c == 0) d_ball[o] = (o < 16) ? bf[o] : ((o < 32) ? bg[o - 16] : bh[o - 32]);
}

// ---------------- xconv: x fp32 [b][c][px] -> bf16 hi/lo [b][px][plane][c] ----------------
__global__ __launch_bounds__(256) void xconv_kernel(const float* __restrict__ x) {
    __shared__ float tx[32][65];
    const int px0 = blockIdx.x * 64;
    const int c0  = blockIdx.y * 32;
    const int b   = blockIdx.z;
    const int tid = threadIdx.x;
    const float* xb = x + (size_t)b * CIN * HW_;
#pragma unroll
    for (int it = 0; it < 8; it++) {
        int e = tid + 256 * it;
        int c = e >> 6, p = e & 63;
        tx[c][p] = xb[(size_t)(c0 + c) * HW_ + px0 + p];
    }
    __syncthreads();
    uint32_t* dst = (uint32_t*)d_xt;
#pragma unroll
    for (int it = 0; it < 8; it++) {
        int e = tid + 256 * it;
        int px = e >> 5, q = e & 31;
        int plane = q >> 4, cp = q & 15;
        float v0 = tx[2 * cp][px], v1 = tx[2 * cp + 1][px];
        float h0 = bfv(v0), h1 = bfv(v1);
        uint32_t outw = plane ? pack_b2(v0 - h0, v1 - h1) : pack_b2(h0, h1);
        size_t idx = (((size_t)b * HW_ + px0 + px) * 512 + plane * 256 + c0 + 2 * cp) >> 1;
        dst[idx] = outw;
    }
}

// ---------------- proj GEMM on tensor cores (bf16 x3) ----------------
#define PX_STRIDE 144
#define PW_STRIDE 144
#define PX_SZ     (128 * PX_STRIDE)
#define PW_OFF    (2 * PX_SZ)
#define PW_SZ     (288 * PW_STRIDE)
#define PROJ_SMEM (PW_OFF + 2 * PW_SZ)

__device__ __forceinline__ void proj_load(uint32_t sb, int slot, int b, int px0, int kc, int tid) {
    uint32_t xdst = sb + slot * PX_SZ;
    const __nv_bfloat16* xsrc = d_xt + ((size_t)b * HW_ + px0) * 512 + kc;
#pragma unroll
    for (int j = 0; j < 4; j++) {
        int e = tid * 4 + j;
        int px = e >> 3, sub = e & 7;
        int pl = sub >> 2, c16 = sub & 3;
        CP16(xdst + px * PX_STRIDE + pl * 64 + c16 * 16, xsrc + (size_t)px * 512 + pl * 256 + c16 * 8);
    }
    uint32_t wdst = sb + PW_OFF + slot * PW_SZ;
    const __nv_bfloat16* wsrc = d_wt + kc;
#pragma unroll
    for (int it = 0; it < 9; it++) {
        int e = tid + 256 * it;
        int o = e >> 3, sub = e & 7;
        int pl = sub >> 2, c16 = sub & 3;
        CP16(wdst + o * PW_STRIDE + pl * 64 + c16 * 16, wsrc + (size_t)o * 512 + pl * 256 + c16 * 8);
    }
    CP_COMMIT();
}

__global__ __launch_bounds__(256, 1) void proj_mma_kernel() {
    extern __shared__ char smraw[];
    const uint32_t sb = smem_u32(smraw);
    const int tid = threadIdx.x, wid = tid >> 5, lane = tid & 31;
    const int t4 = lane & 3, r4 = lane >> 2;
    const int oh = wid & 1, pq = wid >> 1;
    const int px0 = blockIdx.x * 128;
    const int b = blockIdx.y;

    float acc[9][4][4];
#pragma unroll
    for (int mt = 0; mt < 9; mt++)
#pragma unroll
        for (int nt = 0; nt < 4; nt++) { acc[mt][nt][0] = acc[mt][nt][1] = acc[mt][nt][2] = acc[mt][nt][3] = 0.f; }

    proj_load(sb, 0, b, px0, 0, tid);

    for (int ch = 0; ch < 8; ch++) {
        CP_WAIT0();
        __syncthreads();
        if (ch + 1 < 8) proj_load(sb, (ch + 1) & 1, b, px0, (ch + 1) * 32, tid);

        const uint32_t xs = sb + (ch & 1) * PX_SZ;
        const uint32_t ws = sb + PW_OFF + (ch & 1) * PW_SZ;
#pragma unroll
        for (int ks = 0; ks < 2; ks++) {
            uint32_t bh[4][2], bl[4][2];
#pragma unroll
            for (int nt = 0; nt < 4; nt++) {
                uint32_t base = xs + (pq * 32 + nt * 8 + r4) * PX_STRIDE + ks * 32 + t4 * 4;
                bh[nt][0] = lds32(base);       bh[nt][1] = lds32(base + 16);
                bl[nt][0] = lds32(base + 64);  bl[nt][1] = lds32(base + 80);
            }
#pragma unroll
            for (int mt = 0; mt < 9; mt++) {
                uint32_t base = ws + (oh * 144 + mt * 16 + r4) * PW_STRIDE + ks * 32 + t4 * 4;
                uint32_t Ah[4], Al[4];
                Ah[0] = lds32(base);                 Ah[1] = lds32(base + 8 * PW_STRIDE);
                Ah[2] = lds32(base + 16);            Ah[3] = lds32(base + 8 * PW_STRIDE + 16);
                Al[0] = lds32(base + 64);            Al[1] = lds32(base + 8 * PW_STRIDE + 64);
                Al[2] = lds32(base + 80);            Al[3] = lds32(base + 8 * PW_STRIDE + 80);
#pragma unroll
                for (int nt = 0; nt < 4; nt++) {
                    mma_ba(acc[mt][nt], Ah, bh[nt][0], bh[nt][1]);
                    mma_ba(acc[mt][nt], Al, bh[nt][0], bh[nt][1]);
                    mma_ba(acc[mt][nt], Ah, bl[nt][0], bl[nt][1]);
                }
            }
        }
        __syncthreads();
    }

#pragma unroll
    for (int mt = 0; mt < 9; mt++) {
#pragma unroll
        for (int nt = 0; nt < 4; nt++) {
            int px = pq * 32 + nt * 8 + 2 * t4;
#pragma unroll
            for (int r = 0; r < 2; r++) {
                int o = oh * 144 + mt * 16 + r4 + 8 * r;
                float bias = d_ball[o];
                float va = acc[mt][nt][2 * r]     + bias;
                float vb = acc[mt][nt][2 * r + 1] + bias;
                if (oh == 0 && mt == 0) {
                    size_t base = ((size_t)b * HW_ + px0 + px) * 32;
                    float ha = bfv(va), hb = bfv(vb);
                    d_fkm[base + o]      = __float2bfloat16(ha);
                    d_fkm[base + 16 + o] = __float2bfloat16(va - ha);
                    d_fkm[base + 32 + o] = __float2bfloat16(hb);
                    d_fkm[base + 48 + o] = __float2bfloat16(vb - hb);
                } else if (oh == 0 && mt == 1) {
                    float2 st; st.x = va; st.y = vb;
                    *(float2*)&d_gbuf[((size_t)b * DQK + (o - 16)) * HW_ + px0 + px] = st;
                } else {
                    int c = o - 32;
                    int pxp = (px & ~15) | kperm(px & 15);
                    *(uint32_t*)&d_hh[((size_t)b * CIN + c) * HW_ + px0 + pxp] = pack_h2(va, vb);
                }
            }
        }
    }
}

// ---------------- attention: 512 threads, 16 warps = 4 qgroups x 4 subs ----------------
// QK: warp (qg,sub) -> 32 queries x 16 keys. PV: 32 queries x 64 channels.
#define FROW 80
#define FSZ  5120
#define VROW 160
#define VSZ  40960
#define PROW 160
#define PSZ  20480
#define OFF_F 0
#define OFF_V 15360
#define OFF_P 138240
#define OFF_RS 179200
#define SMEM_BYTES (179200 + 2048)

__device__ __forceinline__ void load_tile(uint32_t sb, int slot,
                                          const __nv_bfloat16* fkm, const __half* vb,
                                          int m0, int tid) {
    if (tid < 256) {
        int key = tid >> 2, g = tid & 3;
        CP16(sb + OFF_F + slot * FSZ + key * FROW + g * 16, fkm + (size_t)(m0 + key) * 32 + g * 8);
    }
    uint32_t vdst = sb + OFF_V + slot * VSZ;
#pragma unroll
    for (int j = 0; j < 4; j++) {
        int i = tid + 512 * j;
        int row = i >> 3, c = i & 7;
        CP16(vdst + row * VROW + c * 16, vb + (size_t)row * HW_ + m0 + c * 8);
    }
    CP_COMMIT();
}

__device__ __forceinline__ void load_f(uint32_t sb, int slot,
                                       const __nv_bfloat16* fkm, int m0, int tid) {
    if (tid < 128) {
        int key = tid >> 1, g = tid & 1;
        CP16(sb + OFF_F + slot * FSZ + key * FROW + g * 16, fkm + (size_t)(m0 + key) * 32 + g * 8);
    }
    CP_COMMIT();
}

// QK (bf16 x3, 16 keys) + softmax + P store
__device__ __forceinline__ void qk_tile(uint32_t sb, int fslot, int pslot,
                                        const uint32_t qh[2][4], const uint32_t ql[2][4],
                                        const float negml[2][2], float rs[2][2],
                                        int sub, int t4, int r4, int qbase) {
    const uint32_t fb_ = sb + OFF_F + fslot * FSZ + (sub * 16 + r4) * FROW + t4 * 4;
    float s[2][2][4];
#pragma unroll
    for (int nt = 0; nt < 2; nt++) {
        uint32_t ar = fb_ + nt * 8 * FROW;
        uint32_t bh0 = lds32(ar), bh1 = lds32(ar + 16);
        uint32_t bl0 = lds32(ar + 32), bl1 = lds32(ar + 48);
        mma_bz(s[0][nt], qh[0], bh0, bh1);
        mma_bz(s[1][nt], qh[1], bh0, bh1);
        mma_ba(s[0][nt], ql[0], bh0, bh1);
        mma_ba(s[1][nt], ql[1], bh0, bh1);
        mma_ba(s[0][nt], qh[0], bl0, bl1);
        mma_ba(s[1][nt], qh[1], bl0, bl1);
    }
    const uint32_t pbase = sb + OFF_P + pslot * PSZ + qbase * PROW;
    const uint32_t poff = sub * 32 + t4 * 8;
#pragma unroll
    for (int qt = 0; qt < 2; qt++) {
        uint32_t prow = pbase + (qt * 16 + r4) * PROW;
#pragma unroll
        for (int nt = 0; nt < 2; nt++) {
            float pa0 = ex2(fmaf(s[qt][nt][0], L2E, negml[qt][0]));
            float pa1 = ex2(fmaf(s[qt][nt][1], L2E, negml[qt][0]));
            float pb0 = ex2(fmaf(s[qt][nt][2], L2E, negml[qt][1]));
            float pb1 = ex2(fmaf(s[qt][nt][3], L2E, negml[qt][1]));
            rs[qt][0] += pa0 + pa1;
            rs[qt][1] += pb0 + pb1;
            uint32_t off = poff + nt * 4;
            sts32(prow + off, pack_h2(pa0, pa1));
            sts32(prow + 8 * PROW + off, pack_h2(pb0, pb1));
        }
    }
}

// PV (fp16): 32 queries x 64 channels per warp
__device__ __forceinline__ void pv_tile(uint32_t sb, int vslot, int pslot,
                                        float acc0[8][4], float acc1[8][4],
                                        int sub, int t4, int r4, int qbase) {
    const uint32_t pbase = sb + OFF_P + pslot * PSZ + qbase * PROW;
    const uint32_t vrow = sb + OFF_V + vslot * VSZ + (sub * 64 + r4) * VROW + t4 * 8;
#pragma unroll
    for (int ks = 0; ks < 4; ks++) {
        uint32_t A0[4], A1[4];
        uint32_t pr = pbase + r4 * PROW + ks * 32 + t4 * 8;
        lds64(A0[0], A0[2], pr);
        lds64(A0[1], A0[3], pr + 8 * PROW);
        lds64(A1[0], A1[2], pr + 16 * PROW);
        lds64(A1[1], A1[3], pr + 24 * PROW);
        const uint32_t vk = vrow + ks * 32;
#pragma unroll
        for (int ct = 0; ct < 8; ct++) {
            uint32_t b0, b1;
            lds64(b0, b1, vk + ct * 8 * VROW);
            mma_h16(acc0[ct], A0, b0, b1);
            mma_h16(acc1[ct], A1, b0, b1);
        }
    }
}

__global__ __launch_bounds__(512, 1) void attn_kernel(const float* __restrict__ x,
                                                      const float* __restrict__ gamma_p,
                                                      float* __restrict__ out) {
    extern __shared__ char smraw[];
    const uint32_t sb = smem_u32(smraw);
    float* rsm = (float*)(smraw + OFF_RS);
    const int tid = threadIdx.x, wid = tid >> 5, lane = tid & 31;
    const int t4 = lane & 3, r4 = lane >> 2;
    const int qg = wid >> 2, sub = wid & 3;
    const int qbase = qg * 32;
    const int b = blockIdx.y, n0 = blockIdx.x * 128;

    const float*         gb  = d_gbuf + (size_t)b * DQK * HW_;
    const __nv_bfloat16* fkm = d_fkm + (size_t)b * HW_ * 32;
    const __half*        vbp = d_hh  + (size_t)b * CIN * HW_;

    // ---- Q fragments: bf16 hi/lo ----
    uint32_t qh[2][4], ql[2][4];
#pragma unroll
    for (int qt = 0; qt < 2; qt++) {
        const int nq = n0 + qbase + qt * 16 + r4;
#pragma unroll
        for (int h = 0; h < 2; h++) {
            int k0 = 2 * t4 + 8 * h;
            float va0 = gb[(size_t)k0 * HW_ + nq];
            float va1 = gb[(size_t)(k0 + 1) * HW_ + nq];
            float vb0 = gb[(size_t)k0 * HW_ + nq + 8];
            float vb1 = gb[(size_t)(k0 + 1) * HW_ + nq + 8];
            float ha0 = bfv(va0), ha1 = bfv(va1), hb0 = bfv(vb0), hb1 = bfv(vb1);
            qh[qt][2 * h]     = pack_b2(ha0, ha1);
            qh[qt][2 * h + 1] = pack_b2(hb0, hb1);
            ql[qt][2 * h]     = pack_b2(va0 - ha0, va1 - ha1);
            ql[qt][2 * h + 1] = pack_b2(vb0 - hb0, vb1 - hb1);
        }
    }

    // ================= PREPASS: exact per-row max (bf16 hi, 16 keys per warp) =================
    float smax[2][2] = {{-1e30f, -1e30f}, {-1e30f, -1e30f}};
    load_f(sb, 0, fkm, 0, tid);
    load_f(sb, 1, fkm, 64, tid);
    for (int i = 0; i < 64; i++) {
        CP_WAIT0();
        __syncthreads();
        if (i + 2 < 64) load_f(sb, (i + 2) % 3, fkm, (i + 2) * 64, tid);
        const uint32_t fb_ = sb + OFF_F + (i % 3) * FSZ + (sub * 16 + r4) * FROW + t4 * 4;
#pragma unroll
        for (int nt = 0; nt < 2; nt++) {
            uint32_t ar = fb_ + nt * 8 * FROW;
            uint32_t b0 = lds32(ar), b1 = lds32(ar + 16);
            float s0[4], s1[4];
            mma_bz(s0, qh[0], b0, b1);
            mma_bz(s1, qh[1], b0, b1);
            smax[0][0] = fmaxf(smax[0][0], fmaxf(s0[0], s0[1]));
            smax[0][1] = fmaxf(smax[0][1], fmaxf(s0[2], s0[3]));
            smax[1][0] = fmaxf(smax[1][0], fmaxf(s1[0], s1[1]));
            smax[1][1] = fmaxf(smax[1][1], fmaxf(s1[2], s1[3]));
        }
    }
#pragma unroll
    for (int qt = 0; qt < 2; qt++)
#pragma unroll
        for (int j = 0; j < 2; j++) {
            float m = smax[qt][j];
            m = fmaxf(m, __shfl_xor_sync(0xffffffffu, m, 1));
            m = fmaxf(m, __shfl_xor_sync(0xffffffffu, m, 2));
            smax[qt][j] = m;
        }
    __syncthreads();
    if (t4 == 0) {
#pragma unroll
        for (int qt = 0; qt < 2; qt++) {
            rsm[sub * 128 + qbase + qt * 16 + r4]     = smax[qt][0];
            rsm[sub * 128 + qbase + qt * 16 + r4 + 8] = smax[qt][1];
        }
    }
    __syncthreads();
    float negml[2][2];
#pragma unroll
    for (int qt = 0; qt < 2; qt++) {
#pragma unroll
        for (int j = 0; j < 2; j++) {
            int row = qbase + qt * 16 + r4 + 8 * j;
            float m = fmaxf(fmaxf(rsm[row], rsm[128 + row]),
                            fmaxf(rsm[256 + row], rsm[384 + row]));
            negml[qt][j] = PSHIFT - m * L2E;
        }
    }

    // ================= MAIN LOOP (1 sync/tile) =================
    float acc0[8][4], acc1[8][4];
#pragma unroll
    for (int ct = 0; ct < 8; ct++) {
        acc0[ct][0] = acc0[ct][1] = acc0[ct][2] = acc0[ct][3] = 0.f;
        acc1[ct][0] = acc1[ct][1] = acc1[ct][2] = acc1[ct][3] = 0.f;
    }
    float rs[2][2] = {{0.f, 0.f}, {0.f, 0.f}};

    load_tile(sb, 0, fkm, vbp, 0, tid);
    load_tile(sb, 1, fkm, vbp, 64, tid);
    CP_WAIT1();
    __syncthreads();
    qk_tile(sb, 0, 0, qh, ql, negml, rs, sub, t4, r4, qbase);

    for (int i = 0; i < 64; i++) {
        CP_WAIT0();
        __syncthreads();
        if (i + 2 < 64) load_tile(sb, (i + 2) % 3, fkm, vbp, (i + 2) * 64, tid);
        if (i + 1 < 64) qk_tile(sb, (i + 1) % 3, (i + 1) & 1, qh, ql, negml, rs, sub, t4, r4, qbase);
        pv_tile(sb, i % 3, i & 1, acc0, acc1, sub, t4, r4, qbase);
    }

    // ---- combine row sums across the four key-quarters ----
    __syncthreads();
#pragma unroll
    for (int qt = 0; qt < 2; qt++) {
        float r0 = rs[qt][0], r1 = rs[qt][1];
        r0 += __shfl_xor_sync(0xffffffffu, r0, 1); r0 += __shfl_xor_sync(0xffffffffu, r0, 2);
        r1 += __shfl_xor_sync(0xffffffffu, r1, 1); r1 += __shfl_xor_sync(0xffffffffu, r1, 2);
        if (t4 == 0) {
            rsm[sub * 128 + qbase + qt * 16 + r4]     = r0;
            rsm[sub * 128 + qbase + qt * 16 + r4 + 8] = r1;
        }
    }
    __syncthreads();

    // ---- epilogue ----
    const float gm = *gamma_p;
    const float* xb = x + (size_t)b * CIN * HW_;
    float* ob = out + (size_t)b * CIN * HW_;
#pragma unroll
    for (int qt = 0; qt < 2; qt++) {
        float (*acc)[4] = qt ? acc1 : acc0;
        int qa = qbase + qt * 16 + r4, qb2 = qa + 8;
        float suma = rsm[qa] + rsm[128 + qa] + rsm[256 + qa] + rsm[384 + qa];
        float sumb = rsm[qb2] + rsm[128 + qb2] + rsm[256 + qb2] + rsm[384 + qb2];
        float inva = gm / suma;
        float invb = gm / sumb;
        int na = n0 + qa, nb = n0 + qb2;
#pragma unroll
        for (int ct = 0; ct < 8; ct++) {
            int ch0 = sub * 64 + ct * 8 + 2 * t4, ch1 = ch0 + 1;
            ob[(size_t)ch0 * HW_ + na] = fmaf(inva, acc[ct][0], xb[(size_t)ch0 * HW_ + na]);
            ob[(size_t)ch1 * HW_ + na] = fmaf(inva, acc[ct][1], xb[(size_t)ch1 * HW_ + na]);
            ob[(size_t)ch0 * HW_ + nb] = fmaf(invb, acc[ct][2], xb[(size_t)ch0 * HW_ + nb]);
            ob[(size_t)ch1 * HW_ + nb] = fmaf(invb, acc[ct][3], xb[(size_t)ch1 * HW_ + nb]);
        }
    }
}

// ---------------- launch ----------------
extern "C" void kernel_launch(void* const* d_in, const int* in_sizes, int n_in,
                              void* d_out, int out_size) {
    const float* x  = (const float*)d_in[0];
    const float* Wf = (const float*)d_in[1];
    const float* bf = (const float*)d_in[2];
    const float* Wg = (const float*)d_in[3];
    const float* bg = (const float*)d_in[4];
    const float* Wh = (const float*)d_in[5];
    const float* bh = (const float*)d_in[6];
    const float* gamma = (const float*)d_in[7];
    float* out = (float*)d_out;

    prep_kernel<<<(NO_ * CIN + 255) / 256, 256>>>(Wf, bf, Wg, bg, Wh, bh);
    xconv_kernel<<<dim3(HW_ / 64, CIN / 32, B_), 256>>>(x);

    cudaFuncSetAttribute(proj_mma_kernel, cudaFuncAttributeMaxDynamicSharedMemorySize, PROJ_SMEM);
    proj_mma_kernel<<<dim3(HW_ / 128, B_), 256, PROJ_SMEM>>>();

    cudaFuncSetAttribute(attn_kernel, cudaFuncAttributeMaxDynamicSharedMemorySize, SMEM_BYTES);
    attn_kernel<<<dim3(HW_ / 128, B_), 512, SMEM_BYTES>>>(x, gamma, out);
}